// round 7
// baseline (speedup 1.0000x reference)
#include <cuda_runtime.h>
#include <cuda_fp16.h>
#include <cstdint>

#define NN   4096
#define DD   16
#define BB   32
#define CI   32
#define CO   32
#define JTOT (BB*CI)     // 1024
#define KIO  (2*CI*CO)   // 2048

// ---------------- scratch ----------------
__device__ float  g_P [(size_t)NN*NN];     // 64MB  fp32 relu(E E^T) logits (phase1 scratch)
__device__ __half g_Ph[(size_t)NN*NN];     // 32MB  fp16 exp(v - rowmax)
__device__ float  g_rinv[NN];              // 1/rowsum(exp(v - rowmax))
__device__ float  g_Y [(size_t)NN*JTOT];   // 16MB  Ph @ X (unnormalized)
__device__ float  g_W [(size_t)NN*KIO];    // 32MB
__device__ __half g_Xt[(size_t)JTOT*NN];   // 8MB   Xt[j][m] = fp16(x[b,m,c]), j=b*32+c

// ---------------- helpers ----------------
__device__ __forceinline__ uint32_t smem_u32(const void* p) {
    uint32_t a;
    asm("{ .reg .u64 t; cvta.to.shared.u64 t, %1; cvt.u32.u64 %0, t; }" : "=r"(a) : "l"(p));
    return a;
}
// exp(v) for v <= ~0, FFMA-only; i = floor so f in [0,1)
__device__ __forceinline__ float fast_exp(float v) {
    float y = v * 1.4426950408889634f;
    int   i = __float2int_rd(y);
    float f = y - (float)i;
    float p = 1.5252733804059838e-5f;
    p = fmaf(p, f, 1.5403530393381608e-4f);
    p = fmaf(p, f, 1.3333558146428443e-3f);
    p = fmaf(p, f, 9.6181291076284772e-3f);
    p = fmaf(p, f, 5.5504108664821580e-2f);
    p = fmaf(p, f, 2.4022650695910071e-1f);
    p = fmaf(p, f, 6.9314718055994531e-1f);
    p = fmaf(p, f, 1.0f);
    return p * __int_as_float((i + 127) << 23);
}
union F2 { float2 f; unsigned long long u; };
__device__ __forceinline__ F2 dup2(float v) { F2 r; asm("mov.b64 %0, {%1, %1};" : "=l"(r.u) : "f"(v)); return r; }
__device__ __forceinline__ void fma2(F2& c, F2 a, F2 b) {
    asm("fma.rn.f32x2 %0, %1, %2, %0;" : "+l"(c.u) : "l"(a.u), "l"(b.u));
}
__device__ __forceinline__ void cp16(uint32_t dst, const void* src) {
    asm volatile("cp.async.cg.shared.global [%0], [%1], 16;" :: "r"(dst), "l"(src));
}
__device__ __forceinline__ void ldm4(uint32_t* r, uint32_t addr) {
    asm volatile("ldmatrix.sync.aligned.m8n8.x4.shared.b16 {%0,%1,%2,%3}, [%4];"
                 : "=r"(r[0]), "=r"(r[1]), "=r"(r[2]), "=r"(r[3]) : "r"(addr));
}
__device__ __forceinline__ void mma_f16(float* c, const uint32_t* a, const uint32_t* b) {
    asm volatile(
        "mma.sync.aligned.m16n8k16.row.col.f32.f16.f16.f32 "
        "{%0,%1,%2,%3}, {%4,%5,%6,%7}, {%8,%9}, {%0,%1,%2,%3};"
        : "+f"(c[0]), "+f"(c[1]), "+f"(c[2]), "+f"(c[3])
        : "r"(a[0]), "r"(a[1]), "r"(a[2]), "r"(a[3]), "r"(b[0]), "r"(b[1]));
}
#define SWZ128(off) ((off) ^ (((off) >> 3) & 0x70))

// ---- kernel 1: logits -> rowmax -> Ph = fp16(exp(v-max)), rinv = 1/rowsum ----
__global__ void __launch_bounds__(256) k_supports(const float* __restrict__ E) {
    __shared__ float es[4*DD];
    __shared__ float red[4][8];
    __shared__ float rowmax[4];
    const int tid = threadIdx.x;
    const int n0  = blockIdx.x * 4;

    if (tid < 4*DD) es[tid] = E[n0*DD + tid];
    __syncthreads();
    float ereg[4][DD];
    #pragma unroll
    for (int r = 0; r < 4; r++)
        #pragma unroll
        for (int d = 0; d < DD; d++) ereg[r][d] = es[r*DD + d];

    // phase 1: logits + running max
    float mx[4] = {0.f, 0.f, 0.f, 0.f};
    for (int m2 = tid; m2 < NN/2; m2 += 256) {
        const float4* e4 = reinterpret_cast<const float4*>(E + (size_t)(2*m2)*DD);
        float4 u0 = e4[0], u1 = e4[1], u2 = e4[2], u3 = e4[3];
        float4 v0 = e4[4], v1 = e4[5], v2 = e4[6], v3 = e4[7];
        float a0[DD] = {u0.x,u0.y,u0.z,u0.w, u1.x,u1.y,u1.z,u1.w,
                        u2.x,u2.y,u2.z,u2.w, u3.x,u3.y,u3.z,u3.w};
        float a1[DD] = {v0.x,v0.y,v0.z,v0.w, v1.x,v1.y,v1.z,v1.w,
                        v2.x,v2.y,v2.z,v2.w, v3.x,v3.y,v3.z,v3.w};
        #pragma unroll
        for (int r = 0; r < 4; r++) {
            float d0 = 0.f, d1 = 0.f;
            #pragma unroll
            for (int t = 0; t < DD; t++) {
                d0 = fmaf(a0[t], ereg[r][t], d0);
                d1 = fmaf(a1[t], ereg[r][t], d1);
            }
            d0 = fmaxf(d0, 0.f); d1 = fmaxf(d1, 0.f);
            *reinterpret_cast<float2*>(&g_P[(size_t)(n0 + r)*NN + 2*m2]) = make_float2(d0, d1);
            mx[r] = fmaxf(mx[r], fmaxf(d0, d1));
        }
    }
    #pragma unroll
    for (int r = 0; r < 4; r++) {
        float s = mx[r];
        #pragma unroll
        for (int o = 16; o > 0; o >>= 1) s = fmaxf(s, __shfl_xor_sync(0xffffffffu, s, o));
        if ((tid & 31) == 0) red[r][tid >> 5] = s;
    }
    __syncthreads();
    if (tid < 4) {
        float t = red[tid][0];
        #pragma unroll
        for (int w = 1; w < 8; w++) t = fmaxf(t, red[tid][w]);
        rowmax[tid] = t;
    }
    __syncthreads();
    float rm[4];
    #pragma unroll
    for (int r = 0; r < 4; r++) rm[r] = rowmax[r];

    // phase 2: exp(v - max) -> fp16, rowsum (logit rows L2-hot)
    float sum[4] = {0.f, 0.f, 0.f, 0.f};
    for (int m2 = tid; m2 < NN/2; m2 += 256) {
        #pragma unroll
        for (int r = 0; r < 4; r++) {
            float2 d = *reinterpret_cast<const float2*>(&g_P[(size_t)(n0 + r)*NN + 2*m2]);
            float p0 = fast_exp(d.x - rm[r]);
            float p1 = fast_exp(d.y - rm[r]);
            __half2 h = __floats2half2_rn(p0, p1);
            *reinterpret_cast<__half2*>(&g_Ph[(size_t)(n0 + r)*NN + 2*m2]) = h;
            sum[r] += __half2float(__low2half(h)) + __half2float(__high2half(h));
        }
    }
    __syncthreads();
    #pragma unroll
    for (int r = 0; r < 4; r++) {
        float s = sum[r];
        #pragma unroll
        for (int o = 16; o > 0; o >>= 1) s += __shfl_xor_sync(0xffffffffu, s, o);
        if ((tid & 31) == 0) red[r][tid >> 5] = s;
    }
    __syncthreads();
    if (tid < 4) {
        float t = 0.f;
        #pragma unroll
        for (int w = 0; w < 8; w++) t += red[tid][w];
        g_rinv[n0 + tid] = 1.0f / t;
    }
}

// ---------------- kernel 1b: Xt[j][m] = fp16(x[b,m,c]) ----------------
__global__ void __launch_bounds__(256) k_tr(const float* __restrict__ x) {
    __shared__ float s[32*33];
    const int tid = threadIdx.x;
    const int b   = blockIdx.y;
    const int m0  = blockIdx.x * 32;
    #pragma unroll
    for (int q = 0; q < 4; q++) {
        int idx = tid + q*256;
        int m = idx >> 5, c = idx & 31;
        s[c*33 + m] = x[(size_t)b*NN*CI + (size_t)(m0 + m)*CI + c];
    }
    __syncthreads();
    #pragma unroll
    for (int q = 0; q < 2; q++) {
        int idx2 = tid + q*256;
        int jl = idx2 >> 4, mo2 = idx2 & 15;
        __half2 h = __floats2half2_rn(s[jl*33 + 2*mo2], s[jl*33 + 2*mo2 + 1]);
        *reinterpret_cast<__half2*>(&g_Xt[(size_t)(b*32 + jl)*NN + m0 + 2*mo2]) = h;
    }
}

// ------- kernel 2: fp16 mma.sync GEMM, CTA 128x128, 256 CTAs, 2 CTA/SM -------
#define NITER   (NN/64)          // 64
#define STAGEB  32768            // 16KB A + 16KB B
#define SM_DATA 1024
#define NSTAGE  3
#define GSMEM   (SM_DATA + NSTAGE*STAGEB)   // 99328

__device__ __forceinline__ void issue_loads(uint32_t sbase, int stage, int n0, int col0,
                                            int k0, int tid) {
    const uint32_t sa = sbase + SM_DATA + stage*STAGEB;
    const uint32_t sb = sa + 16384;
    #pragma unroll
    for (int q = 0; q < 4; q++) {                      // A: 128 rows x 64 halves
        int gid = tid + q*256;
        int row = gid >> 3, g = gid & 7;
        uint32_t off = row*128 + g*16;
        cp16(sa + SWZ128(off), g_Ph + (size_t)(n0 + row)*NN + k0 + g*8);
    }
    #pragma unroll
    for (int q = 0; q < 4; q++) {                      // B: 128 rows x 64 halves
        int gid = tid + q*256;
        int row = gid >> 3, g = gid & 7;
        uint32_t off = row*128 + g*16;
        cp16(sb + SWZ128(off), g_Xt + (size_t)(col0 + row)*NN + k0 + g*8);
    }
    asm volatile("cp.async.commit_group;" ::: "memory");
}

__global__ void __launch_bounds__(256, 2) k_gemm() {
    extern __shared__ __align__(1024) uint8_t dsm[];
    const uint32_t sbase = smem_u32(dsm);
    const int tid  = threadIdx.x;
    const int wid  = tid >> 5;
    const int lane = tid & 31;
    const int col0 = blockIdx.x * 128;
    const int n0   = blockIdx.y * 128;

    const int wm = (wid & 3) * 32;         // 4 warps along M
    const int wn = (wid >> 2) * 64;        // 2 warps along N
    const int r   = lane >> 2;
    const int kg  = lane & 3;

    // A tiles (2 x m16): ldmatrix lane addressing
    uint32_t aBase[2], aXor[2];
    {
        int rl = (lane & 7) + ((lane >> 3) & 1) * 8;
        #pragma unroll
        for (int t = 0; t < 2; t++) {
            int row = wm + t*16 + rl;
            aBase[t] = (uint32_t)(row * 128);
            aXor[t]  = (uint32_t)((row & 7) << 4);
        }
    }
    const uint32_t aKc = (uint32_t)(((lane >> 4) & 1) * 16);
    // B pairs (4 x 2n8): lanes 0-7 n+0..7/kc0, 8-15 n+0..7/kc1, 16-23 n+8..15/kc0, 24-31 n+8..15/kc1
    uint32_t bBase[4], bXor[4];
    {
        int jl = ((lane >> 4) & 1) * 8 + (lane & 7);
        #pragma unroll
        for (int p = 0; p < 4; p++) {
            int jr = wn + p*16 + jl;
            bBase[p] = 16384u + (uint32_t)(jr * 128);
            bXor[p]  = (uint32_t)((jr & 7) << 4);
        }
    }
    const uint32_t bKc = (uint32_t)(((lane >> 3) & 1) * 16);

    float acc[2][8][4];
    #pragma unroll
    for (int t = 0; t < 2; t++)
        #pragma unroll
        for (int nt = 0; nt < 8; nt++)
            #pragma unroll
            for (int e = 0; e < 4; e++) acc[t][nt][e] = 0.f;

    issue_loads(sbase, 0, n0, col0, 0,  tid);
    issue_loads(sbase, 1, n0, col0, 64, tid);

    for (int i = 0; i < NITER; i++) {
        asm volatile("cp.async.wait_group 1;" ::: "memory");
        __syncthreads();
        int nstage = i + 2;
        issue_loads(sbase, nstage % NSTAGE, n0, col0, ((nstage) & (NITER-1))*64, tid);

        const uint32_t cur = sbase + SM_DATA + (i % NSTAGE)*STAGEB;
        #pragma unroll
        for (int ks = 0; ks < 4; ks++) {
            const uint32_t ka = (uint32_t)(ks*32) + aKc;
            const uint32_t kb = (uint32_t)(ks*32) + bKc;
            uint32_t a[2][4];
            #pragma unroll
            for (int t = 0; t < 2; t++)
                ldm4(a[t], cur + aBase[t] + (ka ^ aXor[t]));
            uint32_t b[8][2];
            #pragma unroll
            for (int p = 0; p < 4; p++) {
                uint32_t rr[4];
                ldm4(rr, cur + bBase[p] + (kb ^ bXor[p]));
                b[2*p][0]   = rr[0]; b[2*p][1]   = rr[1];
                b[2*p+1][0] = rr[2]; b[2*p+1][1] = rr[3];
            }
            #pragma unroll
            for (int t = 0; t < 2; t++)
                #pragma unroll
                for (int nt = 0; nt < 8; nt++)
                    mma_f16(acc[t][nt], a[t], b[nt]);
        }
    }
    asm volatile("cp.async.wait_group 0;" ::: "memory");

    #pragma unroll
    for (int t = 0; t < 2; t++) {
        const int row = n0 + wm + t*16 + r;
        #pragma unroll
        for (int nt = 0; nt < 8; nt++) {
            const int col = col0 + wn + nt*8 + kg*2;
            *reinterpret_cast<float2*>(&g_Y[(size_t)row*JTOT + col]) =
                make_float2(acc[t][nt][0], acc[t][nt][1]);
            *reinterpret_cast<float2*>(&g_Y[(size_t)(row+8)*JTOT + col]) =
                make_float2(acc[t][nt][2], acc[t][nt][3]);
        }
    }
}

// ---------------- kernel 3: W[n][kio] = sum_d E[n][d] * wp[d][kio] ---------
__global__ void __launch_bounds__(256) k_wgen(const float* __restrict__ E,
                                              const float* __restrict__ wp) {
    const int col = blockIdx.x * 256 + threadIdx.x;
    const int n0  = blockIdx.y * 128;
    __shared__ float es[128 * DD];
    for (int t = threadIdx.x; t < 128*DD; t += 256) es[t] = E[n0*DD + t];
    float w[DD];
    #pragma unroll
    for (int d = 0; d < DD; d++) w[d] = wp[d*KIO + col];
    __syncthreads();
    #pragma unroll 4
    for (int n = 0; n < 128; n++) {
        float acc = 0.f;
        #pragma unroll
        for (int d = 0; d < DD; d++) acc = fmaf(es[n*DD + d], w[d], acc);
        g_W[(size_t)(n0 + n)*KIO + col] = acc;
    }
}

// ------- kernel 4: epilogue, 4 nodes/block, cp.async double-buffered -------
#define ONODES 4
__global__ void __launch_bounds__(256) k_out(const float* __restrict__ x,
                                             const float* __restrict__ bp,
                                             const float* __restrict__ E,
                                             float* __restrict__ out) {
    __shared__ __align__(16) float sws[2][KIO];    // 16KB
    __shared__ __align__(16) float sys[2][JTOT];   // 8KB
    __shared__ __align__(16) float sxs[2][JTOT];   // 8KB
    const int tid   = threadIdx.x;
    const int nbase = blockIdx.x * ONODES;

    auto issue = [&](int s) {
        const int n   = nbase + s;
        const int buf = s & 1;
        uint32_t wdst = smem_u32(&sws[buf][0]);
        uint32_t ydst = smem_u32(&sys[buf][0]);
        uint32_t xdst = smem_u32(&sxs[buf][0]);
        cp16(wdst + (uint32_t)tid*16,        g_W + (size_t)n*KIO + tid*4);
        cp16(wdst + (uint32_t)(tid+256)*16,  g_W + (size_t)n*KIO + (tid+256)*4);
        cp16(ydst + (uint32_t)tid*16,        g_Y + (size_t)n*JTOT + tid*4);
        int b = tid >> 3, i0 = (tid & 7)*4;
        cp16(xdst + (uint32_t)tid*16,        x + (size_t)b*NN*CI + (size_t)n*CI + i0);
        asm volatile("cp.async.commit_group;" ::: "memory");
    };

    issue(0);
    for (int s = 0; s < ONODES; s++) {
        if (s + 1 < ONODES) {
            issue(s + 1);
            asm volatile("cp.async.wait_group 1;" ::: "memory");
        } else {
            asm volatile("cp.async.wait_group 0;" ::: "memory");
        }
        __syncthreads();

        const int n   = nbase + s;
        const int buf = s & 1;
        const float rinv = g_rinv[n];
        const int o  = (tid & 15)*2;
        const int bq = tid >> 4;

        // bias for this thread's two outputs (E/bp broadcast, L2-hot)
        float bo0 = 0.f, bo1 = 0.f;
        #pragma unroll
        for (int d = 0; d < DD; d++) {
            float e = E[n*DD + d];
            bo0 = fmaf(e, bp[d*CO + o],     bo0);
            bo1 = fmaf(e, bp[d*CO + o + 1], bo1);
        }

        const float* ws = sws[buf];
        const float* ys = sys[buf];
        const float* xs = sxs[buf];
        #pragma unroll
        for (int rep = 0; rep < 2; rep++) {
            const int b = bq + rep*16;
            F2 cx0, cx1, cy0, cy1;
            cx0.u = cx1.u = cy0.u = cy1.u = 0ull;
            #pragma unroll
            for (int i = 0; i < CI; i += 2) {
                F2 xv0 = dup2(xs[b*32 + i]);
                F2 xv1 = dup2(xs[b*32 + i + 1]);
                F2 yv0 = dup2(ys[b*32 + i]);
                F2 yv1 = dup2(ys[b*32 + i + 1]);
                F2 w00, w01, w10, w11;
                w00.f = *reinterpret_cast<const float2*>(&ws[i*32 + o]);
                w01.f = *reinterpret_cast<const float2*>(&ws[(i+1)*32 + o]);
                w10.f = *reinterpret_cast<const float2*>(&ws[1024 + i*32 + o]);
                w11.f = *reinterpret_cast<const float2*>(&ws[1024 + (i+1)*32 + o]);
                fma2(cx0, xv0, w00);
                fma2(cx1, xv1, w01);
                fma2(cy0, yv0, w10);
                fma2(cy1, yv1, w11);
            }
            float r0 = (cx0.f.x + cx1.f.x) + rinv*(cy0.f.x + cy1.f.x) + bo0;
            float r1 = (cx0.f.y + cx1.f.y) + rinv*(cy0.f.y + cy1.f.y) + bo1;
            *reinterpret_cast<float2*>(&out[(size_t)b*NN*CO + (size_t)n*CO + o]) = make_float2(r0, r1);
        }
        if (s + 1 < ONODES) __syncthreads();   // compute done before next overwrite
    }
}

// ---------------- launcher -------------------------------------------------
extern "C" void kernel_launch(void* const* d_in, const int* in_sizes, int n_in,
                              void* d_out, int out_size) {
    const float* x  = (const float*)d_in[0];
    const float* wp = (const float*)d_in[1];
    const float* bp = (const float*)d_in[2];
    const float* E  = (const float*)d_in[3];
    float* out = (float*)d_out;

    static bool attr_done = false;
    if (!attr_done) {
        cudaFuncSetAttribute(k_gemm, cudaFuncAttributeMaxDynamicSharedMemorySize, GSMEM);
        attr_done = true;
    }

    k_supports<<<NN/4, 256>>>(E);
    dim3 gt(NN/32, BB);
    k_tr<<<gt, 256>>>(x);
    dim3 gw(KIO/256, NN/128);
    k_wgen<<<gw, 256>>>(E, wp);
    dim3 gg(JTOT/128, NN/128);            // (8, 32) = 256 CTAs, 2/SM
    k_gemm<<<gg, 256, GSMEM>>>();
    k_out<<<NN/ONODES, 256>>>(x, bp, E, out);
}

// round 9
// speedup vs baseline: 1.0674x; 1.0674x over previous
#include <cuda_runtime.h>
#include <cuda_fp16.h>
#include <cstdint>

#define NN   4096
#define DD   16
#define BB   32
#define CI   32
#define CO   32
#define JTOT (BB*CI)     // 1024
#define KIO  (2*CI*CO)   // 2048

// ---------------- scratch ----------------
__device__ __half g_Ph[(size_t)NN*NN];     // 32MB  fp16 exp(v - rowmax)
__device__ float  g_rinv[NN];
__device__ float  g_W [(size_t)NN*KIO];    // 32MB  per-node weights [n][k][i][o]
__device__ float  g_bias[(size_t)NN*CO];   // 512KB
__device__ __half g_Xt[(size_t)JTOT*NN];   // 8MB   Xt[j][m] = fp16(x[b,m,c]), j=b*32+c

// ---------------- helpers ----------------
__device__ __forceinline__ uint32_t smem_u32(const void* p) {
    uint32_t a;
    asm("{ .reg .u64 t; cvta.to.shared.u64 t, %1; cvt.u32.u64 %0, t; }" : "=r"(a) : "l"(p));
    return a;
}
// exp(v) for v <= ~0, FFMA-only
__device__ __forceinline__ float fast_exp(float v) {
    float y = v * 1.4426950408889634f;
    int   i = __float2int_rd(y);
    float f = y - (float)i;
    float p = 1.5252733804059838e-5f;
    p = fmaf(p, f, 1.5403530393381608e-4f);
    p = fmaf(p, f, 1.3333558146428443e-3f);
    p = fmaf(p, f, 9.6181291076284772e-3f);
    p = fmaf(p, f, 5.5504108664821580e-2f);
    p = fmaf(p, f, 2.4022650695910071e-1f);
    p = fmaf(p, f, 6.9314718055994531e-1f);
    p = fmaf(p, f, 1.0f);
    return p * __int_as_float((i + 127) << 23);
}
union F2 { float2 f; unsigned long long u; };
__device__ __forceinline__ F2 dup2(float v) { F2 r; asm("mov.b64 %0, {%1, %1};" : "=l"(r.u) : "f"(v)); return r; }
__device__ __forceinline__ void fma2(F2& c, F2 a, F2 b) {
    asm("fma.rn.f32x2 %0, %1, %2, %0;" : "+l"(c.u) : "l"(a.u), "l"(b.u));
}
__device__ __forceinline__ void cp16(uint32_t dst, const void* src) {
    asm volatile("cp.async.cg.shared.global [%0], [%1], 16;" :: "r"(dst), "l"(src));
}
__device__ __forceinline__ void ldm4(uint32_t* r, uint32_t addr) {
    asm volatile("ldmatrix.sync.aligned.m8n8.x4.shared.b16 {%0,%1,%2,%3}, [%4];"
                 : "=r"(r[0]), "=r"(r[1]), "=r"(r[2]), "=r"(r[3]) : "r"(addr));
}
__device__ __forceinline__ void mma_f16(float* c, const uint32_t* a, const uint32_t* b) {
    asm volatile(
        "mma.sync.aligned.m16n8k16.row.col.f32.f16.f16.f32 "
        "{%0,%1,%2,%3}, {%4,%5,%6,%7}, {%8,%9}, {%0,%1,%2,%3};"
        : "+f"(c[0]), "+f"(c[1]), "+f"(c[2]), "+f"(c[3])
        : "r"(a[0]), "r"(a[1]), "r"(a[2]), "r"(a[3]), "r"(b[0]), "r"(b[1]));
}
#define SWZ128(off) ((off) ^ (((off) >> 3) & 0x70))

// ---- kernel 1: smem logits -> rowmax -> Ph=fp16(exp(v-max)), rinv, bias ----
__global__ void __launch_bounds__(256) k_supports(const float* __restrict__ E,
                                                  const float* __restrict__ bp) {
    extern __shared__ float sL[];           // [4][4096] logits, 64KB
    __shared__ float es[4*DD];
    __shared__ float red[4][8];
    __shared__ float rowmax[4];
    const int tid = threadIdx.x;
    const int n0  = blockIdx.x * 4;

    if (tid < 4*DD) es[tid] = E[n0*DD + tid];
    __syncthreads();
    float ereg[4][DD];
    #pragma unroll
    for (int r = 0; r < 4; r++)
        #pragma unroll
        for (int d = 0; d < DD; d++) ereg[r][d] = es[r*DD + d];

    // phase 1: logits into smem + running max
    float mx[4] = {0.f, 0.f, 0.f, 0.f};
    for (int m2 = tid; m2 < NN/2; m2 += 256) {
        const float4* e4 = reinterpret_cast<const float4*>(E + (size_t)(2*m2)*DD);
        float4 u0 = e4[0], u1 = e4[1], u2 = e4[2], u3 = e4[3];
        float4 v0 = e4[4], v1 = e4[5], v2 = e4[6], v3 = e4[7];
        float a0[DD] = {u0.x,u0.y,u0.z,u0.w, u1.x,u1.y,u1.z,u1.w,
                        u2.x,u2.y,u2.z,u2.w, u3.x,u3.y,u3.z,u3.w};
        float a1[DD] = {v0.x,v0.y,v0.z,v0.w, v1.x,v1.y,v1.z,v1.w,
                        v2.x,v2.y,v2.z,v2.w, v3.x,v3.y,v3.z,v3.w};
        #pragma unroll
        for (int r = 0; r < 4; r++) {
            float d0 = 0.f, d1 = 0.f;
            #pragma unroll
            for (int t = 0; t < DD; t++) {
                d0 = fmaf(a0[t], ereg[r][t], d0);
                d1 = fmaf(a1[t], ereg[r][t], d1);
            }
            d0 = fmaxf(d0, 0.f); d1 = fmaxf(d1, 0.f);
            *reinterpret_cast<float2*>(&sL[r*NN + 2*m2]) = make_float2(d0, d1);
            mx[r] = fmaxf(mx[r], fmaxf(d0, d1));
        }
    }
    #pragma unroll
    for (int r = 0; r < 4; r++) {
        float s = mx[r];
        #pragma unroll
        for (int o = 16; o > 0; o >>= 1) s = fmaxf(s, __shfl_xor_sync(0xffffffffu, s, o));
        if ((tid & 31) == 0) red[r][tid >> 5] = s;
    }
    __syncthreads();
    if (tid < 4) {
        float t = red[tid][0];
        #pragma unroll
        for (int w = 1; w < 8; w++) t = fmaxf(t, red[tid][w]);
        rowmax[tid] = t;
    }
    __syncthreads();
    float rm[4];
    #pragma unroll
    for (int r = 0; r < 4; r++) rm[r] = rowmax[r];

    // phase 2: exp(v - max) -> fp16, rowsum (from smem)
    float sum[4] = {0.f, 0.f, 0.f, 0.f};
    for (int m2 = tid; m2 < NN/2; m2 += 256) {
        #pragma unroll
        for (int r = 0; r < 4; r++) {
            float2 d = *reinterpret_cast<const float2*>(&sL[r*NN + 2*m2]);
            float p0 = fast_exp(d.x - rm[r]);
            float p1 = fast_exp(d.y - rm[r]);
            __half2 h = __floats2half2_rn(p0, p1);
            *reinterpret_cast<__half2*>(&g_Ph[(size_t)(n0 + r)*NN + 2*m2]) = h;
            sum[r] += __half2float(__low2half(h)) + __half2float(__high2half(h));
        }
    }
    #pragma unroll
    for (int r = 0; r < 4; r++) {
        float s = sum[r];
        #pragma unroll
        for (int o = 16; o > 0; o >>= 1) s += __shfl_xor_sync(0xffffffffu, s, o);
        if ((tid & 31) == 0) red[r][tid >> 5] = s;
    }
    __syncthreads();
    if (tid < 4) {
        float t = 0.f;
        #pragma unroll
        for (int w = 0; w < 8; w++) t += red[tid][w];
        g_rinv[n0 + tid] = 1.0f / t;
    }
    // bias for these 4 nodes: tid<128 -> (r, o)
    if (tid < 4*CO) {
        int r = tid >> 5, o = tid & 31;
        float acc = 0.f;
        #pragma unroll
        for (int d = 0; d < DD; d++) acc = fmaf(es[r*DD + d], bp[d*CO + o], acc);
        g_bias[(n0 + r)*CO + o] = acc;
    }
}

// ---------------- kernel 1b: Xt[j][m] = fp16(x[b,m,c]) ----------------
__global__ void __launch_bounds__(256) k_tr(const float* __restrict__ x) {
    __shared__ float s[32*33];
    const int tid = threadIdx.x;
    const int b   = blockIdx.y;
    const int m0  = blockIdx.x * 32;
    #pragma unroll
    for (int q = 0; q < 4; q++) {
        int idx = tid + q*256;
        int m = idx >> 5, c = idx & 31;
        s[c*33 + m] = x[(size_t)b*NN*CI + (size_t)(m0 + m)*CI + c];
    }
    __syncthreads();
    #pragma unroll
    for (int q = 0; q < 2; q++) {
        int idx2 = tid + q*256;
        int jl = idx2 >> 4, mo2 = idx2 & 15;
        __half2 h = __floats2half2_rn(s[jl*33 + 2*mo2], s[jl*33 + 2*mo2 + 1]);
        *reinterpret_cast<__half2*>(&g_Xt[(size_t)(b*32 + jl)*NN + m0 + 2*mo2]) = h;
    }
}

// ---------------- kernel 2: W[n][kio] = sum_d E[n][d] * wp[d][kio] ---------
__global__ void __launch_bounds__(256) k_wgen(const float* __restrict__ E,
                                              const float* __restrict__ wp) {
    const int col = blockIdx.x * 256 + threadIdx.x;
    const int n0  = blockIdx.y * 128;
    __shared__ float es[128 * DD];
    for (int t = threadIdx.x; t < 128*DD; t += 256) es[t] = E[n0*DD + t];
    float w[DD];
    #pragma unroll
    for (int d = 0; d < DD; d++) w[d] = wp[d*KIO + col];
    __syncthreads();
    #pragma unroll 4
    for (int n = 0; n < 128; n++) {
        float acc = 0.f;
        #pragma unroll
        for (int d = 0; d < DD; d++) acc = fmaf(es[n*DD + d], w[d], acc);
        g_W[(size_t)(n0 + n)*KIO + col] = acc;
    }
}

// ---- kernel 3: fused GEMM (Ph @ Xt^T) + output epilogue --------------------
// CTA 128x256, BK=64, 4-stage cp.async mainloop; epilogue stages Y tile in
// smem and computes out directly (32 chunks x 4 nodes, W/x double-buffered).
#define NITER   (NN/64)          // 64
#define STAGEB  49152            // 16KB A + 32KB B
#define SM_DATA 1024
// epilogue smem layout (reuses the same dynamic allocation)
#define YROW    264              // floats per ysm row (128 rows)
#define YS_OFF  0                // 128*264*4 = 135168
#define WS_OFF  135168           // 2 x 32768
#define XS_OFF  200704           // 2 x 4096
#define GSMEM   208896

__device__ __forceinline__ void issue_loads(uint32_t sbase, int stage, int n0, int col0,
                                            int k0, int tid) {
    const uint32_t sa = sbase + SM_DATA + stage*STAGEB;
    const uint32_t sb = sa + 16384;
    #pragma unroll
    for (int q = 0; q < 4; q++) {                      // A: 128 rows x 64 halves
        int gid = tid + q*256;
        int row = gid >> 3, g = gid & 7;
        uint32_t off = row*128 + g*16;
        cp16(sa + SWZ128(off), g_Ph + (size_t)(n0 + row)*NN + k0 + g*8);
    }
    #pragma unroll
    for (int q = 0; q < 8; q++) {                      // B: 256 rows x 64 halves
        int gid = tid + q*256;
        int row = gid >> 3, g = gid & 7;
        uint32_t off = row*128 + g*16;
        cp16(sb + SWZ128(off), g_Xt + (size_t)(col0 + row)*NN + k0 + g*8);
    }
    asm volatile("cp.async.commit_group;" ::: "memory");
}

__device__ __forceinline__ void issue_epi(uint32_t sbase, int c, int n0, int b0,
                                          const float* __restrict__ x, int tid) {
    const int buf = c & 1;
    const uint32_t wdst = sbase + WS_OFF + buf*32768;
    const uint32_t xdst = sbase + XS_OFF + buf*4096;
    const int nbase = n0 + c*4;
    #pragma unroll
    for (int q = 0; q < 8; q++) {                      // W: 4 nodes x 8KB, layout [ns][kio]
        int idx = tid + q*256;
        int ns = idx >> 9, w4 = (idx & 511) * 4;
        cp16(wdst + (uint32_t)idx*16, g_W + (size_t)(nbase + ns)*KIO + w4);
    }
    {                                                  // x: layout [ns][b][i] (matches reader!)
        int b = tid >> 5, ns = (tid >> 3) & 3, i0 = (tid & 7)*4;
        cp16(xdst + (uint32_t)(ns*1024 + b*128 + i0*4),
             x + (size_t)(b0 + b)*NN*CI + (size_t)(nbase + ns)*CI + i0);
    }
    asm volatile("cp.async.commit_group;" ::: "memory");
}

__global__ void __launch_bounds__(256, 1) k_gemm(const float* __restrict__ x,
                                                 float* __restrict__ out) {
    extern __shared__ __align__(1024) uint8_t dsm[];
    const uint32_t sbase = smem_u32(dsm);
    const int tid  = threadIdx.x;
    const int wid  = tid >> 5;
    const int lane = tid & 31;
    const int col0 = blockIdx.x * 256;
    const int n0   = blockIdx.y * 128;
    const int b0   = col0 >> 5;

    const int wm = (wid >> 2) * 64;
    const int wn = (wid & 3) * 64;
    const int r   = lane >> 2;
    const int kg  = lane & 3;

    uint32_t aBase[4], aXor[4];
    {
        int rl = (lane & 7) + ((lane >> 3) & 1) * 8;
        #pragma unroll
        for (int t = 0; t < 4; t++) {
            int row = wm + t*16 + rl;
            aBase[t] = (uint32_t)(row * 128);
            aXor[t]  = (uint32_t)((row & 7) << 4);
        }
    }
    const uint32_t aKc = (uint32_t)(((lane >> 4) & 1) * 16);
    uint32_t bBase[4], bXor[4];
    {
        int jl = ((lane >> 4) & 1) * 8 + (lane & 7);
        #pragma unroll
        for (int p = 0; p < 4; p++) {
            int jr = wn + p*16 + jl;
            bBase[p] = 16384u + (uint32_t)(jr * 128);
            bXor[p]  = (uint32_t)((jr & 7) << 4);
        }
    }
    const uint32_t bKc = (uint32_t)(((lane >> 3) & 1) * 16);

    float acc[4][8][4];
    #pragma unroll
    for (int t = 0; t < 4; t++)
        #pragma unroll
        for (int nt = 0; nt < 8; nt++)
            #pragma unroll
            for (int e = 0; e < 4; e++) acc[t][nt][e] = 0.f;

    issue_loads(sbase, 0, n0, col0, 0,   tid);
    issue_loads(sbase, 1, n0, col0, 64,  tid);
    issue_loads(sbase, 2, n0, col0, 128, tid);

    for (int i = 0; i < NITER; i++) {
        asm volatile("cp.async.wait_group 2;" ::: "memory");
        __syncthreads();
        if (i + 3 < NITER) issue_loads(sbase, (i + 3) & 3, n0, col0, (i + 3)*64, tid);

        const uint32_t cur = sbase + SM_DATA + (i & 3)*STAGEB;
        #pragma unroll
        for (int ks = 0; ks < 4; ks++) {
            const uint32_t ka = (uint32_t)(ks*32) + aKc;
            const uint32_t kb = (uint32_t)(ks*32) + bKc;
            uint32_t a[4][4];
            #pragma unroll
            for (int t = 0; t < 4; t++)
                ldm4(a[t], cur + aBase[t] + (ka ^ aXor[t]));
            uint32_t b[8][2];
            #pragma unroll
            for (int p = 0; p < 4; p++) {
                uint32_t rr[4];
                ldm4(rr, cur + bBase[p] + (kb ^ bXor[p]));
                b[2*p][0]   = rr[0]; b[2*p][1]   = rr[1];
                b[2*p+1][0] = rr[2]; b[2*p+1][1] = rr[3];
            }
            #pragma unroll
            for (int t = 0; t < 4; t++)
                #pragma unroll
                for (int nt = 0; nt < 8; nt++)
                    mma_f16(acc[t][nt], a[t], b[nt]);
        }
    }
    asm volatile("cp.async.wait_group 0;" ::: "memory");
    __syncthreads();                 // all smem reads done; safe to overwrite

    // ---- stage Y tile into smem: ysm[row][col], row stride YROW ----
    float* ysm = reinterpret_cast<float*>(dsm + YS_OFF);
    #pragma unroll
    for (int t = 0; t < 4; t++) {
        const int row = wm + t*16 + r;
        #pragma unroll
        for (int nt = 0; nt < 8; nt++) {
            const int col = wn + nt*8 + kg*2;
            *reinterpret_cast<float2*>(&ysm[row*YROW + col]) =
                make_float2(acc[t][nt][0], acc[t][nt][1]);
            *reinterpret_cast<float2*>(&ysm[(row+8)*YROW + col]) =
                make_float2(acc[t][nt][2], acc[t][nt][3]);
        }
    }
    issue_epi(sbase, 0, n0, b0, x, tid);
    issue_epi(sbase, 1, n0, b0, x, tid);
    __syncthreads();                 // ysm visible

    // ---- output epilogue: 32 chunks x 4 nodes ----
    const int g   = tid >> 4;
    const int o   = (tid & 15) * 2;
    const int nsb = g & 3;
    const int bq  = g >> 2;

    for (int c = 0; c < 32; c++) {
        if (c < 31) asm volatile("cp.async.wait_group 1;" ::: "memory");
        else        asm volatile("cp.async.wait_group 0;" ::: "memory");
        __syncthreads();

        const int nl = c*4 + nsb;
        const int n  = n0 + nl;
        const float rinv = g_rinv[n];
        const float2 bias2 = *reinterpret_cast<const float2*>(&g_bias[n*CO + o]);
        const float* ws = reinterpret_cast<const float*>(dsm + WS_OFF + (c & 1)*32768) + nsb*KIO;
        const float* xs = reinterpret_cast<const float*>(dsm + XS_OFF + (c & 1)*4096) + nsb*256;
        const float* yr = ysm + nl*YROW;

        #pragma unroll
        for (int rep = 0; rep < 2; rep++) {
            const int b = bq + rep*4;
            F2 cx0, cx1, cy0, cy1;
            cx0.u = cx1.u = cy0.u = cy1.u = 0ull;
            #pragma unroll
            for (int i = 0; i < CI; i += 2) {
                F2 xv0 = dup2(xs[b*32 + i]);
                F2 xv1 = dup2(xs[b*32 + i + 1]);
                F2 yv0 = dup2(yr[b*32 + i]);
                F2 yv1 = dup2(yr[b*32 + i + 1]);
                F2 w00, w01, w10, w11;
                w00.f = *reinterpret_cast<const float2*>(&ws[i*32 + o]);
                w01.f = *reinterpret_cast<const float2*>(&ws[(i+1)*32 + o]);
                w10.f = *reinterpret_cast<const float2*>(&ws[1024 + i*32 + o]);
                w11.f = *reinterpret_cast<const float2*>(&ws[1024 + (i+1)*32 + o]);
                fma2(cx0, xv0, w00);
                fma2(cx1, xv1, w01);
                fma2(cy0, yv0, w10);
                fma2(cy1, yv1, w11);
            }
            float r0 = (cx0.f.x + cx1.f.x) + rinv*(cy0.f.x + cy1.f.x) + bias2.x;
            float r1 = (cx0.f.y + cx1.f.y) + rinv*(cy0.f.y + cy1.f.y) + bias2.y;
            *reinterpret_cast<float2*>(&out[(size_t)(b0 + b)*NN*CO + (size_t)n*CO + o]) =
                make_float2(r0, r1);
        }
        __syncthreads();
        if (c + 2 < 32) issue_epi(sbase, c + 2, n0, b0, x, tid);
    }
}

// ---------------- launcher -------------------------------------------------
extern "C" void kernel_launch(void* const* d_in, const int* in_sizes, int n_in,
                              void* d_out, int out_size) {
    const float* x  = (const float*)d_in[0];
    const float* wp = (const float*)d_in[1];
    const float* bp = (const float*)d_in[2];
    const float* E  = (const float*)d_in[3];
    float* out = (float*)d_out;

    static bool attr_done = false;
    if (!attr_done) {
        cudaFuncSetAttribute(k_gemm,     cudaFuncAttributeMaxDynamicSharedMemorySize, GSMEM);
        cudaFuncSetAttribute(k_supports, cudaFuncAttributeMaxDynamicSharedMemorySize, 65536);
        attr_done = true;
    }

    k_supports<<<NN/4, 256, 65536>>>(E, bp);
    dim3 gt(NN/32, BB);
    k_tr<<<gt, 256>>>(x);
    dim3 gw(KIO/256, NN/128);
    k_wgen<<<gw, 256>>>(E, wp);
    dim3 gg(JTOT/256, NN/128);            // (4, 32) = 128 CTAs
    k_gemm<<<gg, 256, GSMEM>>>(x, out);
}

// round 10
// speedup vs baseline: 1.1199x; 1.0492x over previous
#include <cuda_runtime.h>
#include <cuda_fp16.h>
#include <cstdint>

#define NN   4096
#define DD   16
#define BB   32
#define CI   32
#define CO   32
#define JTOT (BB*CI)     // 1024
#define KIO  (2*CI*CO)   // 2048

// ---------------- scratch ----------------
__device__ __half g_Ph[(size_t)NN*NN];     // 32MB  fp16 exp(v - rowmax)
__device__ float  g_rinv[NN];
__device__ __half g_Wh[(size_t)NN*KIO];    // 16MB  per-node weights fp16 [n][k][i][o]
__device__ float  g_bias[(size_t)NN*CO];   // 512KB
__device__ __half g_Xt[(size_t)JTOT*NN];   // 8MB   Xt[j][m] = fp16(x[b,m,c]), j=b*32+c

// ---------------- helpers ----------------
__device__ __forceinline__ uint32_t smem_u32(const void* p) {
    uint32_t a;
    asm("{ .reg .u64 t; cvta.to.shared.u64 t, %1; cvt.u32.u64 %0, t; }" : "=r"(a) : "l"(p));
    return a;
}
union F2 { float2 f; unsigned long long u; };
__device__ __forceinline__ F2 dup2(float v) { F2 r; asm("mov.b64 %0, {%1, %1};" : "=l"(r.u) : "f"(v)); return r; }
__device__ __forceinline__ void fma2(F2& c, F2 a, F2 b) {
    asm("fma.rn.f32x2 %0, %1, %2, %0;" : "+l"(c.u) : "l"(a.u), "l"(b.u));
}
__device__ __forceinline__ void cp16(uint32_t dst, const void* src) {
    asm volatile("cp.async.cg.shared.global [%0], [%1], 16;" :: "r"(dst), "l"(src));
}
__device__ __forceinline__ void ldm4(uint32_t* r, uint32_t addr) {
    asm volatile("ldmatrix.sync.aligned.m8n8.x4.shared.b16 {%0,%1,%2,%3}, [%4];"
                 : "=r"(r[0]), "=r"(r[1]), "=r"(r[2]), "=r"(r[3]) : "r"(addr));
}
__device__ __forceinline__ void mma_f16(float* c, const uint32_t* a, const uint32_t* b) {
    asm volatile(
        "mma.sync.aligned.m16n8k16.row.col.f32.f16.f16.f32 "
        "{%0,%1,%2,%3}, {%4,%5,%6,%7}, {%8,%9}, {%0,%1,%2,%3};"
        : "+f"(c[0]), "+f"(c[1]), "+f"(c[2]), "+f"(c[3])
        : "r"(a[0]), "r"(a[1]), "r"(a[2]), "r"(a[3]), "r"(b[0]), "r"(b[1]));
}
#define SWZ128(off) ((off) ^ (((off) >> 3) & 0x70))

// ---- kernel 1: smem logits -> rowmax -> Ph=fp16(exp(v-max)), rinv, bias ----
__global__ void __launch_bounds__(256) k_supports(const float* __restrict__ E,
                                                  const float* __restrict__ bp) {
    extern __shared__ float sL[];           // [4][4096] logits, 64KB
    __shared__ float es[4*DD];
    __shared__ float red[4][8];
    __shared__ float rowmax[4];
    const int tid = threadIdx.x;
    const int n0  = blockIdx.x * 4;

    if (tid < 4*DD) es[tid] = E[n0*DD + tid];
    __syncthreads();
    float ereg[4][DD];
    #pragma unroll
    for (int r = 0; r < 4; r++)
        #pragma unroll
        for (int d = 0; d < DD; d++) ereg[r][d] = es[r*DD + d];

    // phase 1: logits into smem + running max
    float mx[4] = {0.f, 0.f, 0.f, 0.f};
    for (int m2 = tid; m2 < NN/2; m2 += 256) {
        const float4* e4 = reinterpret_cast<const float4*>(E + (size_t)(2*m2)*DD);
        float4 u0 = e4[0], u1 = e4[1], u2 = e4[2], u3 = e4[3];
        float4 v0 = e4[4], v1 = e4[5], v2 = e4[6], v3 = e4[7];
        float a0[DD] = {u0.x,u0.y,u0.z,u0.w, u1.x,u1.y,u1.z,u1.w,
                        u2.x,u2.y,u2.z,u2.w, u3.x,u3.y,u3.z,u3.w};
        float a1[DD] = {v0.x,v0.y,v0.z,v0.w, v1.x,v1.y,v1.z,v1.w,
                        v2.x,v2.y,v2.z,v2.w, v3.x,v3.y,v3.z,v3.w};
        #pragma unroll
        for (int r = 0; r < 4; r++) {
            float d0 = 0.f, d1 = 0.f;
            #pragma unroll
            for (int t = 0; t < DD; t++) {
                d0 = fmaf(a0[t], ereg[r][t], d0);
                d1 = fmaf(a1[t], ereg[r][t], d1);
            }
            d0 = fmaxf(d0, 0.f); d1 = fmaxf(d1, 0.f);
            *reinterpret_cast<float2*>(&sL[r*NN + 2*m2]) = make_float2(d0, d1);
            mx[r] = fmaxf(mx[r], fmaxf(d0, d1));
        }
    }
    #pragma unroll
    for (int r = 0; r < 4; r++) {
        float s = mx[r];
        #pragma unroll
        for (int o = 16; o > 0; o >>= 1) s = fmaxf(s, __shfl_xor_sync(0xffffffffu, s, o));
        if ((tid & 31) == 0) red[r][tid >> 5] = s;
    }
    __syncthreads();
    if (tid < 4) {
        float t = red[tid][0];
        #pragma unroll
        for (int w = 1; w < 8; w++) t = fmaxf(t, red[tid][w]);
        rowmax[tid] = t;
    }
    __syncthreads();
    float rm[4];
    #pragma unroll
    for (int r = 0; r < 4; r++) rm[r] = rowmax[r];

    // phase 2: exp(v - max) -> fp16 via MUFU, rowsum
    float sum[4] = {0.f, 0.f, 0.f, 0.f};
    for (int m2 = tid; m2 < NN/2; m2 += 256) {
        #pragma unroll
        for (int r = 0; r < 4; r++) {
            float2 d = *reinterpret_cast<const float2*>(&sL[r*NN + 2*m2]);
            float p0 = __expf(d.x - rm[r]);
            float p1 = __expf(d.y - rm[r]);
            __half2 h = __floats2half2_rn(p0, p1);
            *reinterpret_cast<__half2*>(&g_Ph[(size_t)(n0 + r)*NN + 2*m2]) = h;
            sum[r] += __half2float(__low2half(h)) + __half2float(__high2half(h));
        }
    }
    #pragma unroll
    for (int r = 0; r < 4; r++) {
        float s = sum[r];
        #pragma unroll
        for (int o = 16; o > 0; o >>= 1) s += __shfl_xor_sync(0xffffffffu, s, o);
        if ((tid & 31) == 0) red[r][tid >> 5] = s;
    }
    __syncthreads();
    if (tid < 4) {
        float t = 0.f;
        #pragma unroll
        for (int w = 0; w < 8; w++) t += red[tid][w];
        g_rinv[n0 + tid] = 1.0f / t;
    }
    // bias for these 4 nodes
    if (tid < 4*CO) {
        int r = tid >> 5, o = tid & 31;
        float acc = 0.f;
        #pragma unroll
        for (int d = 0; d < DD; d++) acc = fmaf(es[r*DD + d], bp[d*CO + o], acc);
        g_bias[(n0 + r)*CO + o] = acc;
    }
}

// ---------------- kernel 1b: Xt[j][m] = fp16(x[b,m,c]) ----------------
__global__ void __launch_bounds__(256) k_tr(const float* __restrict__ x) {
    __shared__ float s[32*33];
    const int tid = threadIdx.x;
    const int b   = blockIdx.y;
    const int m0  = blockIdx.x * 32;
    #pragma unroll
    for (int q = 0; q < 4; q++) {
        int idx = tid + q*256;
        int m = idx >> 5, c = idx & 31;
        s[c*33 + m] = x[(size_t)b*NN*CI + (size_t)(m0 + m)*CI + c];
    }
    __syncthreads();
    #pragma unroll
    for (int q = 0; q < 2; q++) {
        int idx2 = tid + q*256;
        int jl = idx2 >> 4, mo2 = idx2 & 15;
        __half2 h = __floats2half2_rn(s[jl*33 + 2*mo2], s[jl*33 + 2*mo2 + 1]);
        *reinterpret_cast<__half2*>(&g_Xt[(size_t)(b*32 + jl)*NN + m0 + 2*mo2]) = h;
    }
}

// ------ kernel 2: Wh[n][kio] = fp16(sum_d E[n][d] * wp[d][kio]), half2 ------
__global__ void __launch_bounds__(256) k_wgen(const float* __restrict__ E,
                                              const float* __restrict__ wp) {
    const int col2 = blockIdx.x * 256 + threadIdx.x;   // 0..1023 (pairs)
    const int n0   = blockIdx.y * 128;
    __shared__ float es[128 * DD];
    for (int t = threadIdx.x; t < 128*DD; t += 256) es[t] = E[n0*DD + t];
    float2 w[DD];
    #pragma unroll
    for (int d = 0; d < DD; d++)
        w[d] = *reinterpret_cast<const float2*>(&wp[d*KIO + 2*col2]);
    __syncthreads();
    #pragma unroll 4
    for (int n = 0; n < 128; n++) {
        float a0 = 0.f, a1 = 0.f;
        #pragma unroll
        for (int d = 0; d < DD; d++) {
            float e = es[n*DD + d];
            a0 = fmaf(e, w[d].x, a0);
            a1 = fmaf(e, w[d].y, a1);
        }
        *reinterpret_cast<__half2*>(&g_Wh[(size_t)(n0 + n)*KIO + 2*col2]) =
            __floats2half2_rn(a0, a1);
    }
}

// ---- kernel 3: fused GEMM (Ph @ Xt^T) + output epilogue --------------------
#define NITER   (NN/64)          // 64
#define STAGEB  49152            // 16KB A + 32KB B
#define SM_DATA 1024
// epilogue smem layout (reuses the same dynamic allocation)
#define YROW    264              // floats per ysm row (128 rows)
#define YS_OFF  0                // 128*264*4 = 135168
#define WS_OFF  135168           // 2 x 16384 (fp16 W)
#define XS_OFF  167936           // 2 x 4096
#define GSMEM   (SM_DATA + 4*STAGEB)   // 197632 (mainloop dominates)

__device__ __forceinline__ void issue_loads(uint32_t sbase, int stage, int n0, int col0,
                                            int k0, int tid) {
    const uint32_t sa = sbase + SM_DATA + stage*STAGEB;
    const uint32_t sb = sa + 16384;
    #pragma unroll
    for (int q = 0; q < 4; q++) {                      // A: 128 rows x 64 halves
        int gid = tid + q*256;
        int row = gid >> 3, g = gid & 7;
        uint32_t off = row*128 + g*16;
        cp16(sa + SWZ128(off), g_Ph + (size_t)(n0 + row)*NN + k0 + g*8);
    }
    #pragma unroll
    for (int q = 0; q < 8; q++) {                      // B: 256 rows x 64 halves
        int gid = tid + q*256;
        int row = gid >> 3, g = gid & 7;
        uint32_t off = row*128 + g*16;
        cp16(sb + SWZ128(off), g_Xt + (size_t)(col0 + row)*NN + k0 + g*8);
    }
    asm volatile("cp.async.commit_group;" ::: "memory");
}

__device__ __forceinline__ void issue_epi(uint32_t sbase, int c, int n0, int b0,
                                          const float* __restrict__ x, int tid) {
    const int buf = c & 1;
    const uint32_t wdst = sbase + WS_OFF + buf*16384;
    const uint32_t xdst = sbase + XS_OFF + buf*4096;
    const int nbase = n0 + c*4;
    #pragma unroll
    for (int q = 0; q < 4; q++) {                      // W: 4 nodes x 4KB fp16, [ns][kio]
        int idx = tid + q*256;
        int ns = idx >> 8, h8 = (idx & 255) * 8;
        cp16(wdst + (uint32_t)idx*16, g_Wh + (size_t)(nbase + ns)*KIO + h8);
    }
    {                                                  // x: layout [ns][b][i]
        int b = tid >> 5, ns = (tid >> 3) & 3, i0 = (tid & 7)*4;
        cp16(xdst + (uint32_t)(ns*1024 + b*128 + i0*4),
             x + (size_t)(b0 + b)*NN*CI + (size_t)(nbase + ns)*CI + i0);
    }
    asm volatile("cp.async.commit_group;" ::: "memory");
}

__global__ void __launch_bounds__(256, 1) k_gemm(const float* __restrict__ x,
                                                 float* __restrict__ out) {
    extern __shared__ __align__(1024) uint8_t dsm[];
    const uint32_t sbase = smem_u32(dsm);
    const int tid  = threadIdx.x;
    const int wid  = tid >> 5;
    const int lane = tid & 31;
    const int col0 = blockIdx.x * 256;
    const int n0   = blockIdx.y * 128;
    const int b0   = col0 >> 5;

    const int wm = (wid >> 2) * 64;
    const int wn = (wid & 3) * 64;
    const int r   = lane >> 2;
    const int kg  = lane & 3;

    uint32_t aBase[4], aXor[4];
    {
        int rl = (lane & 7) + ((lane >> 3) & 1) * 8;
        #pragma unroll
        for (int t = 0; t < 4; t++) {
            int row = wm + t*16 + rl;
            aBase[t] = (uint32_t)(row * 128);
            aXor[t]  = (uint32_t)((row & 7) << 4);
        }
    }
    const uint32_t aKc = (uint32_t)(((lane >> 4) & 1) * 16);
    uint32_t bBase[4], bXor[4];
    {
        int jl = ((lane >> 4) & 1) * 8 + (lane & 7);
        #pragma unroll
        for (int p = 0; p < 4; p++) {
            int jr = wn + p*16 + jl;
            bBase[p] = 16384u + (uint32_t)(jr * 128);
            bXor[p]  = (uint32_t)((jr & 7) << 4);
        }
    }
    const uint32_t bKc = (uint32_t)(((lane >> 3) & 1) * 16);

    float acc[4][8][4];
    #pragma unroll
    for (int t = 0; t < 4; t++)
        #pragma unroll
        for (int nt = 0; nt < 8; nt++)
            #pragma unroll
            for (int e = 0; e < 4; e++) acc[t][nt][e] = 0.f;

    issue_loads(sbase, 0, n0, col0, 0,   tid);
    issue_loads(sbase, 1, n0, col0, 64,  tid);
    issue_loads(sbase, 2, n0, col0, 128, tid);

    for (int i = 0; i < NITER; i++) {
        asm volatile("cp.async.wait_group 2;" ::: "memory");
        __syncthreads();
        if (i + 3 < NITER) issue_loads(sbase, (i + 3) & 3, n0, col0, (i + 3)*64, tid);

        const uint32_t cur = sbase + SM_DATA + (i & 3)*STAGEB;
        #pragma unroll
        for (int ks = 0; ks < 4; ks++) {
            const uint32_t ka = (uint32_t)(ks*32) + aKc;
            const uint32_t kb = (uint32_t)(ks*32) + bKc;
            uint32_t a[4][4];
            #pragma unroll
            for (int t = 0; t < 4; t++)
                ldm4(a[t], cur + aBase[t] + (ka ^ aXor[t]));
            uint32_t b[8][2];
            #pragma unroll
            for (int p = 0; p < 4; p++) {
                uint32_t rr[4];
                ldm4(rr, cur + bBase[p] + (kb ^ bXor[p]));
                b[2*p][0]   = rr[0]; b[2*p][1]   = rr[1];
                b[2*p+1][0] = rr[2]; b[2*p+1][1] = rr[3];
            }
            #pragma unroll
            for (int t = 0; t < 4; t++)
                #pragma unroll
                for (int nt = 0; nt < 8; nt++)
                    mma_f16(acc[t][nt], a[t], b[nt]);
        }
    }
    asm volatile("cp.async.wait_group 0;" ::: "memory");
    __syncthreads();                 // all smem reads done; safe to overwrite

    // ---- stage Y tile into smem ----
    float* ysm = reinterpret_cast<float*>(dsm + YS_OFF);
    #pragma unroll
    for (int t = 0; t < 4; t++) {
        const int row = wm + t*16 + r;
        #pragma unroll
        for (int nt = 0; nt < 8; nt++) {
            const int col = wn + nt*8 + kg*2;
            *reinterpret_cast<float2*>(&ysm[row*YROW + col]) =
                make_float2(acc[t][nt][0], acc[t][nt][1]);
            *reinterpret_cast<float2*>(&ysm[(row+8)*YROW + col]) =
                make_float2(acc[t][nt][2], acc[t][nt][3]);
        }
    }
    issue_epi(sbase, 0, n0, b0, x, tid);
    issue_epi(sbase, 1, n0, b0, x, tid);
    __syncthreads();                 // ysm visible

    // ---- output epilogue: 32 chunks x 4 nodes ----
    const int g   = tid >> 4;
    const int o   = (tid & 15) * 2;
    const int nsb = g & 3;
    const int bq  = g >> 2;

    for (int c = 0; c < 32; c++) {
        if (c < 31) asm volatile("cp.async.wait_group 1;" ::: "memory");
        else        asm volatile("cp.async.wait_group 0;" ::: "memory");
        __syncthreads();

        const int nl = c*4 + nsb;
        const int n  = n0 + nl;
        const float rinv = g_rinv[n];
        const float2 bias2 = *reinterpret_cast<const float2*>(&g_bias[n*CO + o]);
        const __half* ws = reinterpret_cast<const __half*>(dsm + WS_OFF + (c & 1)*16384) + nsb*KIO;
        const float*  xs = reinterpret_cast<const float*>(dsm + XS_OFF + (c & 1)*4096) + nsb*256;
        const float*  yr = ysm + nl*YROW;

        #pragma unroll
        for (int rep = 0; rep < 2; rep++) {
            const int b = bq + rep*4;
            F2 cx0, cx1, cy0, cy1;
            cx0.u = cx1.u = cy0.u = cy1.u = 0ull;
            #pragma unroll
            for (int i = 0; i < CI; i += 2) {
                F2 xv0 = dup2(xs[b*32 + i]);
                F2 xv1 = dup2(xs[b*32 + i + 1]);
                F2 yv0 = dup2(yr[b*32 + i]);
                F2 yv1 = dup2(yr[b*32 + i + 1]);
                F2 w00, w01, w10, w11;
                w00.f = __half22float2(*reinterpret_cast<const __half2*>(&ws[i*32 + o]));
                w01.f = __half22float2(*reinterpret_cast<const __half2*>(&ws[(i+1)*32 + o]));
                w10.f = __half22float2(*reinterpret_cast<const __half2*>(&ws[1024 + i*32 + o]));
                w11.f = __half22float2(*reinterpret_cast<const __half2*>(&ws[1024 + (i+1)*32 + o]));
                fma2(cx0, xv0, w00);
                fma2(cx1, xv1, w01);
                fma2(cy0, yv0, w10);
                fma2(cy1, yv1, w11);
            }
            float r0 = (cx0.f.x + cx1.f.x) + rinv*(cy0.f.x + cy1.f.x) + bias2.x;
            float r1 = (cx0.f.y + cx1.f.y) + rinv*(cy0.f.y + cy1.f.y) + bias2.y;
            *reinterpret_cast<float2*>(&out[(size_t)(b0 + b)*NN*CO + (size_t)n*CO + o]) =
                make_float2(r0, r1);
        }
        __syncthreads();
        if (c + 2 < 32) issue_epi(sbase, c + 2, n0, b0, x, tid);
    }
}

// ---------------- launcher -------------------------------------------------
extern "C" void kernel_launch(void* const* d_in, const int* in_sizes, int n_in,
                              void* d_out, int out_size) {
    const float* x  = (const float*)d_in[0];
    const float* wp = (const float*)d_in[1];
    const float* bp = (const float*)d_in[2];
    const float* E  = (const float*)d_in[3];
    float* out = (float*)d_out;

    static bool attr_done = false;
    if (!attr_done) {
        cudaFuncSetAttribute(k_gemm,     cudaFuncAttributeMaxDynamicSharedMemorySize, GSMEM);
        cudaFuncSetAttribute(k_supports, cudaFuncAttributeMaxDynamicSharedMemorySize, 65536);
        attr_done = true;
    }

    k_supports<<<NN/4, 256, 65536>>>(E, bp);
    dim3 gt(NN/32, BB);
    k_tr<<<gt, 256>>>(x);
    dim3 gw(KIO/512, NN/128);             // (4, 32)
    k_wgen<<<gw, 256>>>(E, wp);
    dim3 gg(JTOT/256, NN/128);            // (4, 32) = 128 CTAs
    k_gemm<<<gg, 256, GSMEM>>>(x, out);
}

// round 11
// speedup vs baseline: 1.3157x; 1.1748x over previous
#include <cuda_runtime.h>
#include <cuda_fp16.h>
#include <cstdint>

#define NN   4096
#define DD   16
#define BB   32
#define CI   32
#define CO   32
#define JTOT (BB*CI)     // 1024
#define KIO  (2*CI*CO)   // 2048

// ---------------- scratch ----------------
__device__ __half g_Ph[(size_t)NN*NN];     // 32MB  fp16 exp(v - rowmax)
__device__ float  g_rinv[NN];
__device__ __half g_Wh[(size_t)NN*KIO];    // 16MB  fp16 weights [n][k][i][o]
__device__ float  g_bias[(size_t)NN*CO];   // 512KB
__device__ __half g_Xt[(size_t)JTOT*NN];   // 8MB

// ---------------- helpers ----------------
__device__ __forceinline__ uint32_t smem_u32(const void* p) {
    uint32_t a;
    asm("{ .reg .u64 t; cvta.to.shared.u64 t, %1; cvt.u32.u64 %0, t; }" : "=r"(a) : "l"(p));
    return a;
}
union F2 { float2 f; unsigned long long u; };
__device__ __forceinline__ F2 dup2(float v) { F2 r; asm("mov.b64 %0, {%1, %1};" : "=l"(r.u) : "f"(v)); return r; }
__device__ __forceinline__ void fma2(F2& c, F2 a, F2 b) {
    asm("fma.rn.f32x2 %0, %1, %2, %0;" : "+l"(c.u) : "l"(a.u), "l"(b.u));
}
__device__ __forceinline__ void cp16(uint32_t dst, const void* src) {
    asm volatile("cp.async.cg.shared.global [%0], [%1], 16;" :: "r"(dst), "l"(src));
}
__device__ __forceinline__ void ldm4(uint32_t* r, uint32_t addr) {
    asm volatile("ldmatrix.sync.aligned.m8n8.x4.shared.b16 {%0,%1,%2,%3}, [%4];"
                 : "=r"(r[0]), "=r"(r[1]), "=r"(r[2]), "=r"(r[3]) : "r"(addr));
}
__device__ __forceinline__ void mma_f16(float* c, const uint32_t* a, const uint32_t* b) {
    asm volatile(
        "mma.sync.aligned.m16n8k16.row.col.f32.f16.f16.f32 "
        "{%0,%1,%2,%3}, {%4,%5,%6,%7}, {%8,%9}, {%0,%1,%2,%3};"
        : "+f"(c[0]), "+f"(c[1]), "+f"(c[2]), "+f"(c[3])
        : "r"(a[0]), "r"(a[1]), "r"(a[2]), "r"(a[3]), "r"(b[0]), "r"(b[1]));
}
#define SWZ128(off) ((off) ^ (((off) >> 3) & 0x70))

// ---- kernel 1: 8 rows/block, 128KB smem logits -> Ph, rinv, bias ----
#define SROWS 8
__global__ void __launch_bounds__(256) k_supports(const float* __restrict__ E,
                                                  const float* __restrict__ bp) {
    extern __shared__ float sL[];           // [8][4096] logits, 128KB
    __shared__ float es[SROWS*DD];
    __shared__ float red[SROWS][8];
    __shared__ float rowred[SROWS];
    const int tid = threadIdx.x;
    const int n0  = blockIdx.x * SROWS;

    if (tid < SROWS*DD) es[tid] = E[n0*DD + tid];
    __syncthreads();
    float ereg[SROWS][DD];
    #pragma unroll
    for (int r = 0; r < SROWS; r++)
        #pragma unroll
        for (int d = 0; d < DD; d++) ereg[r][d] = es[r*DD + d];

    // phase 1: logits into smem + running max (1 m per iter)
    float mx[SROWS];
    #pragma unroll
    for (int r = 0; r < SROWS; r++) mx[r] = 0.f;
    for (int m = tid; m < NN; m += 256) {
        const float4* e4 = reinterpret_cast<const float4*>(E + (size_t)m*DD);
        float4 u0 = e4[0], u1 = e4[1], u2 = e4[2], u3 = e4[3];
        float av[DD] = {u0.x,u0.y,u0.z,u0.w, u1.x,u1.y,u1.z,u1.w,
                        u2.x,u2.y,u2.z,u2.w, u3.x,u3.y,u3.z,u3.w};
        #pragma unroll
        for (int r = 0; r < SROWS; r++) {
            float d = 0.f;
            #pragma unroll
            for (int t = 0; t < DD; t++) d = fmaf(av[t], ereg[r][t], d);
            d = fmaxf(d, 0.f);
            sL[r*NN + m] = d;
            mx[r] = fmaxf(mx[r], d);
        }
    }
    #pragma unroll
    for (int r = 0; r < SROWS; r++) {
        float s = mx[r];
        #pragma unroll
        for (int o = 16; o > 0; o >>= 1) s = fmaxf(s, __shfl_xor_sync(0xffffffffu, s, o));
        if ((tid & 31) == 0) red[r][tid >> 5] = s;
    }
    __syncthreads();
    if (tid < SROWS) {
        float t = red[tid][0];
        #pragma unroll
        for (int w = 1; w < 8; w++) t = fmaxf(t, red[tid][w]);
        rowred[tid] = t;
    }
    __syncthreads();
    float rm[SROWS];
    #pragma unroll
    for (int r = 0; r < SROWS; r++) rm[r] = rowred[r];

    // phase 2: exp(v - max) -> fp16, rowsum
    float sum[SROWS];
    #pragma unroll
    for (int r = 0; r < SROWS; r++) sum[r] = 0.f;
    for (int m2 = tid; m2 < NN/2; m2 += 256) {
        #pragma unroll
        for (int r = 0; r < SROWS; r++) {
            float2 d = *reinterpret_cast<const float2*>(&sL[r*NN + 2*m2]);
            float p0 = __expf(d.x - rm[r]);
            float p1 = __expf(d.y - rm[r]);
            __half2 h = __floats2half2_rn(p0, p1);
            *reinterpret_cast<__half2*>(&g_Ph[(size_t)(n0 + r)*NN + 2*m2]) = h;
            sum[r] += __half2float(__low2half(h)) + __half2float(__high2half(h));
        }
    }
    #pragma unroll
    for (int r = 0; r < SROWS; r++) {
        float s = sum[r];
        #pragma unroll
        for (int o = 16; o > 0; o >>= 1) s += __shfl_xor_sync(0xffffffffu, s, o);
        if ((tid & 31) == 0) red[r][tid >> 5] = s;
    }
    __syncthreads();
    if (tid < SROWS) {
        float t = 0.f;
        #pragma unroll
        for (int w = 0; w < 8; w++) t += red[tid][w];
        g_rinv[n0 + tid] = 1.0f / t;
    }
    // bias: all 256 threads: r = tid>>5 (0..7), o = tid&31
    {
        int r = tid >> 5, o = tid & 31;
        float acc = 0.f;
        #pragma unroll
        for (int d = 0; d < DD; d++) acc = fmaf(es[r*DD + d], bp[d*CO + o], acc);
        g_bias[(n0 + r)*CO + o] = acc;
    }
}

// ---------------- kernel 1b: Xt[j][m] = fp16(x[b,m,c]) ----------------
__global__ void __launch_bounds__(256) k_tr(const float* __restrict__ x) {
    __shared__ float s[32*33];
    const int tid = threadIdx.x;
    const int b   = blockIdx.y;
    const int m0  = blockIdx.x * 32;
    #pragma unroll
    for (int q = 0; q < 4; q++) {
        int idx = tid + q*256;
        int m = idx >> 5, c = idx & 31;
        s[c*33 + m] = x[(size_t)b*NN*CI + (size_t)(m0 + m)*CI + c];
    }
    __syncthreads();
    #pragma unroll
    for (int q = 0; q < 2; q++) {
        int idx2 = tid + q*256;
        int jl = idx2 >> 4, mo2 = idx2 & 15;
        __half2 h = __floats2half2_rn(s[jl*33 + 2*mo2], s[jl*33 + 2*mo2 + 1]);
        *reinterpret_cast<__half2*>(&g_Xt[(size_t)(b*32 + jl)*NN + m0 + 2*mo2]) = h;
    }
}

// ------ kernel 2: Wh[n][kio] = fp16(sum_d E[n][d] * wp[d][kio]) ------
__global__ void __launch_bounds__(256) k_wgen(const float* __restrict__ E,
                                              const float* __restrict__ wp) {
    const int col2 = blockIdx.x * 256 + threadIdx.x;
    const int n0   = blockIdx.y * 128;
    __shared__ float es[128 * DD];
    for (int t = threadIdx.x; t < 128*DD; t += 256) es[t] = E[n0*DD + t];
    float2 w[DD];
    #pragma unroll
    for (int d = 0; d < DD; d++)
        w[d] = *reinterpret_cast<const float2*>(&wp[d*KIO + 2*col2]);
    __syncthreads();
    #pragma unroll 4
    for (int n = 0; n < 128; n++) {
        float a0 = 0.f, a1 = 0.f;
        #pragma unroll
        for (int d = 0; d < DD; d++) {
            float e = es[n*DD + d];
            a0 = fmaf(e, w[d].x, a0);
            a1 = fmaf(e, w[d].y, a1);
        }
        *reinterpret_cast<__half2*>(&g_Wh[(size_t)(n0 + n)*KIO + 2*col2]) =
            __floats2half2_rn(a0, a1);
    }
}

// ---- kernel 3: fused GEMM + epilogue (4-buffer, 1 barrier/chunk) ----------
#define NITER   (NN/64)          // 64
#define STAGEB  49152
#define SM_DATA 1024
#define GSMEM   (SM_DATA + 4*STAGEB)   // 197632
// epilogue layout (halfs for Y)
#define YROW    264              // halfs per ysm row
#define YS_OFF  0                // 128*264*2 = 67584
#define WBUF    16896            // 4 nodes x 2080 halfs (pad vs bank conflict)
#define WS_OFF  67584            // 4 x 16896 = 67584 -> ends 135168
#define XS_OFF  135168           // 4 x 4096 -> ends 151552
#define WPAD    2080             // halfs per node in staged W

__device__ __forceinline__ void issue_loads(uint32_t sbase, int stage, int n0, int col0,
                                            int k0, int tid) {
    const uint32_t sa = sbase + SM_DATA + stage*STAGEB;
    const uint32_t sb = sa + 16384;
    #pragma unroll
    for (int q = 0; q < 4; q++) {
        int gid = tid + q*256;
        int row = gid >> 3, g = gid & 7;
        uint32_t off = row*128 + g*16;
        cp16(sa + SWZ128(off), g_Ph + (size_t)(n0 + row)*NN + k0 + g*8);
    }
    #pragma unroll
    for (int q = 0; q < 8; q++) {
        int gid = tid + q*256;
        int row = gid >> 3, g = gid & 7;
        uint32_t off = row*128 + g*16;
        cp16(sb + SWZ128(off), g_Xt + (size_t)(col0 + row)*NN + k0 + g*8);
    }
    asm volatile("cp.async.commit_group;" ::: "memory");
}

__device__ __forceinline__ void issue_epi(uint32_t sbase, int c, int n0, int b0,
                                          const float* __restrict__ x, int tid) {
    const int buf = c & 3;
    const uint32_t wdst = sbase + WS_OFF + buf*WBUF;
    const uint32_t xdst = sbase + XS_OFF + buf*4096;
    const int nbase = n0 + c*4;
    #pragma unroll
    for (int q = 0; q < 4; q++) {                      // W: 4 nodes x 4KB fp16, padded
        int idx = tid + q*256;
        int ns = idx >> 8, h8 = (idx & 255) * 8;
        cp16(wdst + (uint32_t)(ns*(WPAD*2) + h8*2), g_Wh + (size_t)(nbase + ns)*KIO + h8);
    }
    {                                                  // x: [ns][b][i]
        int b = tid >> 5, ns = (tid >> 3) & 3, i0 = (tid & 7)*4;
        cp16(xdst + (uint32_t)(ns*1024 + b*128 + i0*4),
             x + (size_t)(b0 + b)*NN*CI + (size_t)(nbase + ns)*CI + i0);
    }
    asm volatile("cp.async.commit_group;" ::: "memory");
}

__global__ void __launch_bounds__(256, 1) k_gemm(const float* __restrict__ x,
                                                 float* __restrict__ out) {
    extern __shared__ __align__(1024) uint8_t dsm[];
    const uint32_t sbase = smem_u32(dsm);
    const int tid  = threadIdx.x;
    const int wid  = tid >> 5;
    const int lane = tid & 31;
    const int col0 = blockIdx.x * 256;
    const int n0   = blockIdx.y * 128;
    const int b0   = col0 >> 5;

    const int wm = (wid >> 2) * 64;
    const int wn = (wid & 3) * 64;
    const int r   = lane >> 2;
    const int kg  = lane & 3;

    uint32_t aBase[4], aXor[4];
    {
        int rl = (lane & 7) + ((lane >> 3) & 1) * 8;
        #pragma unroll
        for (int t = 0; t < 4; t++) {
            int row = wm + t*16 + rl;
            aBase[t] = (uint32_t)(row * 128);
            aXor[t]  = (uint32_t)((row & 7) << 4);
        }
    }
    const uint32_t aKc = (uint32_t)(((lane >> 4) & 1) * 16);
    uint32_t bBase[4], bXor[4];
    {
        int jl = ((lane >> 4) & 1) * 8 + (lane & 7);
        #pragma unroll
        for (int p = 0; p < 4; p++) {
            int jr = wn + p*16 + jl;
            bBase[p] = 16384u + (uint32_t)(jr * 128);
            bXor[p]  = (uint32_t)((jr & 7) << 4);
        }
    }
    const uint32_t bKc = (uint32_t)(((lane >> 3) & 1) * 16);

    float acc[4][8][4];
    #pragma unroll
    for (int t = 0; t < 4; t++)
        #pragma unroll
        for (int nt = 0; nt < 8; nt++)
            #pragma unroll
            for (int e = 0; e < 4; e++) acc[t][nt][e] = 0.f;

    issue_loads(sbase, 0, n0, col0, 0,   tid);
    issue_loads(sbase, 1, n0, col0, 64,  tid);
    issue_loads(sbase, 2, n0, col0, 128, tid);

    for (int i = 0; i < NITER; i++) {
        asm volatile("cp.async.wait_group 2;" ::: "memory");
        __syncthreads();
        if (i + 3 < NITER) issue_loads(sbase, (i + 3) & 3, n0, col0, (i + 3)*64, tid);

        const uint32_t cur = sbase + SM_DATA + (i & 3)*STAGEB;
        #pragma unroll
        for (int ks = 0; ks < 4; ks++) {
            const uint32_t ka = (uint32_t)(ks*32) + aKc;
            const uint32_t kb = (uint32_t)(ks*32) + bKc;
            uint32_t a[4][4];
            #pragma unroll
            for (int t = 0; t < 4; t++)
                ldm4(a[t], cur + aBase[t] + (ka ^ aXor[t]));
            uint32_t b[8][2];
            #pragma unroll
            for (int p = 0; p < 4; p++) {
                uint32_t rr[4];
                ldm4(rr, cur + bBase[p] + (kb ^ bXor[p]));
                b[2*p][0]   = rr[0]; b[2*p][1]   = rr[1];
                b[2*p+1][0] = rr[2]; b[2*p+1][1] = rr[3];
            }
            #pragma unroll
            for (int t = 0; t < 4; t++)
                #pragma unroll
                for (int nt = 0; nt < 8; nt++)
                    mma_f16(acc[t][nt], a[t], b[nt]);
        }
    }
    asm volatile("cp.async.wait_group 0;" ::: "memory");
    __syncthreads();

    // ---- stage Y tile into smem as fp16 ----
    __half* ysm = reinterpret_cast<__half*>(dsm + YS_OFF);
    #pragma unroll
    for (int t = 0; t < 4; t++) {
        const int row = wm + t*16 + r;
        #pragma unroll
        for (int nt = 0; nt < 8; nt++) {
            const int col = wn + nt*8 + kg*2;
            *reinterpret_cast<__half2*>(&ysm[row*YROW + col]) =
                __floats2half2_rn(acc[t][nt][0], acc[t][nt][1]);
            *reinterpret_cast<__half2*>(&ysm[(row+8)*YROW + col]) =
                __floats2half2_rn(acc[t][nt][2], acc[t][nt][3]);
        }
    }
    issue_epi(sbase, 0, n0, b0, x, tid);
    issue_epi(sbase, 1, n0, b0, x, tid);
    issue_epi(sbase, 2, n0, b0, x, tid);

    // ---- output epilogue: 32 chunks x 4 nodes, ONE barrier per chunk ----
    const int g   = tid >> 4;
    const int o   = (tid & 15) * 2;
    const int nsb = g & 3;
    const int bq  = g >> 2;

    for (int c = 0; c < 32; c++) {
        if      (c <= 29) asm volatile("cp.async.wait_group 2;" ::: "memory");
        else if (c == 30) asm volatile("cp.async.wait_group 1;" ::: "memory");
        else              asm volatile("cp.async.wait_group 0;" ::: "memory");
        __syncthreads();   // group c visible to all; all threads done with chunk c-1
        if (c + 3 < 32) issue_epi(sbase, c + 3, n0, b0, x, tid);

        const int nl = c*4 + nsb;
        const int n  = n0 + nl;
        const float rinv = g_rinv[n];
        const float2 bias2 = *reinterpret_cast<const float2*>(&g_bias[n*CO + o]);
        const __half* ws = reinterpret_cast<const __half*>(dsm + WS_OFF + (c & 3)*WBUF) + nsb*WPAD;
        const float*  xs = reinterpret_cast<const float*>(dsm + XS_OFF + (c & 3)*4096) + nsb*256;
        const __half* yr = reinterpret_cast<const __half*>(dsm + YS_OFF) + nl*YROW;

        #pragma unroll
        for (int rep = 0; rep < 2; rep++) {
            const int b = bq + rep*4;
            F2 cx0, cx1, cy0, cy1;
            cx0.u = cx1.u = cy0.u = cy1.u = 0ull;
            #pragma unroll
            for (int i = 0; i < CI; i += 2) {
                float2 xv = *reinterpret_cast<const float2*>(&xs[b*32 + i]);
                float2 yv = __half22float2(*reinterpret_cast<const __half2*>(&yr[b*32 + i]));
                F2 w00, w01, w10, w11;
                w00.f = __half22float2(*reinterpret_cast<const __half2*>(&ws[i*32 + o]));
                w01.f = __half22float2(*reinterpret_cast<const __half2*>(&ws[(i+1)*32 + o]));
                w10.f = __half22float2(*reinterpret_cast<const __half2*>(&ws[1024 + i*32 + o]));
                w11.f = __half22float2(*reinterpret_cast<const __half2*>(&ws[1024 + (i+1)*32 + o]));
                fma2(cx0, dup2(xv.x), w00);
                fma2(cx1, dup2(xv.y), w01);
                fma2(cy0, dup2(yv.x), w10);
                fma2(cy1, dup2(yv.y), w11);
            }
            float r0 = (cx0.f.x + cx1.f.x) + rinv*(cy0.f.x + cy1.f.x) + bias2.x;
            float r1 = (cx0.f.y + cx1.f.y) + rinv*(cy0.f.y + cy1.f.y) + bias2.y;
            *reinterpret_cast<float2*>(&out[(size_t)(b0 + b)*NN*CO + (size_t)n*CO + o]) =
                make_float2(r0, r1);
        }
    }
}

// ---------------- launcher -------------------------------------------------
extern "C" void kernel_launch(void* const* d_in, const int* in_sizes, int n_in,
                              void* d_out, int out_size) {
    const float* x  = (const float*)d_in[0];
    const float* wp = (const float*)d_in[1];
    const float* bp = (const float*)d_in[2];
    const float* E  = (const float*)d_in[3];
    float* out = (float*)d_out;

    static bool attr_done = false;
    if (!attr_done) {
        cudaFuncSetAttribute(k_gemm,     cudaFuncAttributeMaxDynamicSharedMemorySize, GSMEM);
        cudaFuncSetAttribute(k_supports, cudaFuncAttributeMaxDynamicSharedMemorySize, 131072);
        attr_done = true;
    }

    k_supports<<<NN/SROWS, 256, 131072>>>(E, bp);
    dim3 gt(NN/32, BB);
    k_tr<<<gt, 256>>>(x);
    dim3 gw(KIO/512, NN/128);
    k_wgen<<<gw, 256>>>(E, wp);
    dim3 gg(JTOT/256, NN/128);            // (4, 32) = 128 CTAs
    k_gemm<<<gg, 256, GSMEM>>>(x, out);
}

// round 14
// speedup vs baseline: 1.3387x; 1.0175x over previous
#include <cuda_runtime.h>
#include <cuda_fp16.h>
#include <cstdint>

#define NN   4096
#define DD   16
#define BB   32
#define CI   32
#define CO   32
#define JTOT (BB*CI)     // 1024
#define KIO  (2*CI*CO)   // 2048

// ---------------- scratch ----------------
__device__ __half g_Ph[(size_t)NN*NN];     // 32MB  fp16 exp(v - rowmax)
__device__ float  g_rinv[NN];
__device__ __half g_Wh[(size_t)NN*KIO];    // 16MB  fp16 weights [n][i'=k*32+i][o]
__device__ float  g_bias[(size_t)NN*CO];   // 512KB
__device__ __half g_Xt[(size_t)JTOT*NN];   // 8MB   Xt[j][m], j=b*32+c  (GEMM B operand)
__device__ __half g_Xn[(size_t)NN*JTOT];   // 8MB   Xn[m][b*32+c]      (epilogue A operand)

// ---------------- helpers ----------------
__device__ __forceinline__ uint32_t smem_u32(const void* p) {
    uint32_t a;
    asm("{ .reg .u64 t; cvta.to.shared.u64 t, %1; cvt.u32.u64 %0, t; }" : "=r"(a) : "l"(p));
    return a;
}
__device__ __forceinline__ void cp16(uint32_t dst, const void* src) {
    asm volatile("cp.async.cg.shared.global [%0], [%1], 16;" :: "r"(dst), "l"(src));
}
__device__ __forceinline__ void ldm4(uint32_t* r, uint32_t addr) {
    asm volatile("ldmatrix.sync.aligned.m8n8.x4.shared.b16 {%0,%1,%2,%3}, [%4];"
                 : "=r"(r[0]), "=r"(r[1]), "=r"(r[2]), "=r"(r[3]) : "r"(addr));
}
__device__ __forceinline__ void ldm4t(uint32_t* r, uint32_t addr) {
    asm volatile("ldmatrix.sync.aligned.m8n8.x4.trans.shared.b16 {%0,%1,%2,%3}, [%4];"
                 : "=r"(r[0]), "=r"(r[1]), "=r"(r[2]), "=r"(r[3]) : "r"(addr));
}
__device__ __forceinline__ void ldm2(uint32_t& r0, uint32_t& r1, uint32_t addr) {
    asm volatile("ldmatrix.sync.aligned.m8n8.x2.shared.b16 {%0,%1}, [%2];"
                 : "=r"(r0), "=r"(r1) : "r"(addr));
}
__device__ __forceinline__ void mma_f16(float* c, const uint32_t* a, const uint32_t* b) {
    asm volatile(
        "mma.sync.aligned.m16n8k16.row.col.f32.f16.f16.f32 "
        "{%0,%1,%2,%3}, {%4,%5,%6,%7}, {%8,%9}, {%0,%1,%2,%3};"
        : "+f"(c[0]), "+f"(c[1]), "+f"(c[2]), "+f"(c[3])
        : "r"(a[0]), "r"(a[1]), "r"(a[2]), "r"(a[3]), "r"(b[0]), "r"(b[1]));
}
#define SWZ128(off) ((off) ^ (((off) >> 3) & 0x70))

// ---- kernel 1: 8 rows/block, 128KB smem logits -> Ph, rinv, bias ----
#define SROWS 8
__global__ void __launch_bounds__(256) k_supports(const float* __restrict__ E,
                                                  const float* __restrict__ bp) {
    extern __shared__ float sL[];
    __shared__ float es[SROWS*DD];
    __shared__ float red[SROWS][8];
    __shared__ float rowred[SROWS];
    const int tid = threadIdx.x;
    const int n0  = blockIdx.x * SROWS;

    if (tid < SROWS*DD) es[tid] = E[n0*DD + tid];
    __syncthreads();
    float ereg[SROWS][DD];
    #pragma unroll
    for (int r = 0; r < SROWS; r++)
        #pragma unroll
        for (int d = 0; d < DD; d++) ereg[r][d] = es[r*DD + d];

    float mx[SROWS];
    #pragma unroll
    for (int r = 0; r < SROWS; r++) mx[r] = 0.f;
    for (int m = tid; m < NN; m += 256) {
        const float4* e4 = reinterpret_cast<const float4*>(E + (size_t)m*DD);
        float4 u0 = e4[0], u1 = e4[1], u2 = e4[2], u3 = e4[3];
        float av[DD] = {u0.x,u0.y,u0.z,u0.w, u1.x,u1.y,u1.z,u1.w,
                        u2.x,u2.y,u2.z,u2.w, u3.x,u3.y,u3.z,u3.w};
        #pragma unroll
        for (int r = 0; r < SROWS; r++) {
            float d = 0.f;
            #pragma unroll
            for (int t = 0; t < DD; t++) d = fmaf(av[t], ereg[r][t], d);
            d = fmaxf(d, 0.f);
            sL[r*NN + m] = d;
            mx[r] = fmaxf(mx[r], d);
        }
    }
    #pragma unroll
    for (int r = 0; r < SROWS; r++) {
        float s = mx[r];
        #pragma unroll
        for (int o = 16; o > 0; o >>= 1) s = fmaxf(s, __shfl_xor_sync(0xffffffffu, s, o));
        if ((tid & 31) == 0) red[r][tid >> 5] = s;
    }
    __syncthreads();
    if (tid < SROWS) {
        float t = red[tid][0];
        #pragma unroll
        for (int w = 1; w < 8; w++) t = fmaxf(t, red[tid][w]);
        rowred[tid] = t;
    }
    __syncthreads();
    float rm[SROWS];
    #pragma unroll
    for (int r = 0; r < SROWS; r++) rm[r] = rowred[r];

    float sum[SROWS];
    #pragma unroll
    for (int r = 0; r < SROWS; r++) sum[r] = 0.f;
    for (int m2 = tid; m2 < NN/2; m2 += 256) {
        #pragma unroll
        for (int r = 0; r < SROWS; r++) {
            float2 d = *reinterpret_cast<const float2*>(&sL[r*NN + 2*m2]);
            float p0 = __expf(d.x - rm[r]);
            float p1 = __expf(d.y - rm[r]);
            __half2 h = __floats2half2_rn(p0, p1);
            *reinterpret_cast<__half2*>(&g_Ph[(size_t)(n0 + r)*NN + 2*m2]) = h;
            sum[r] += __half2float(__low2half(h)) + __half2float(__high2half(h));
        }
    }
    #pragma unroll
    for (int r = 0; r < SROWS; r++) {
        float s = sum[r];
        #pragma unroll
        for (int o = 16; o > 0; o >>= 1) s += __shfl_xor_sync(0xffffffffu, s, o);
        if ((tid & 31) == 0) red[r][tid >> 5] = s;
    }
    __syncthreads();
    if (tid < SROWS) {
        float t = 0.f;
        #pragma unroll
        for (int w = 0; w < 8; w++) t += red[tid][w];
        g_rinv[n0 + tid] = 1.0f / t;
    }
    {
        int r = tid >> 5, o = tid & 31;
        float acc = 0.f;
        #pragma unroll
        for (int d = 0; d < DD; d++) acc = fmaf(es[r*DD + d], bp[d*CO + o], acc);
        g_bias[(n0 + r)*CO + o] = acc;
    }
}

// ---- kernel 1b: Xt[j][m] and Xn[m][j] = fp16(x[b,m,c]) ----
__global__ void __launch_bounds__(256) k_tr(const float* __restrict__ x) {
    __shared__ float s[32*33];
    const int tid = threadIdx.x;
    const int b   = blockIdx.y;
    const int m0  = blockIdx.x * 32;
    #pragma unroll
    for (int q = 0; q < 4; q++) {
        int idx = tid + q*256;
        int m = idx >> 5, c = idx & 31;
        s[c*33 + m] = x[(size_t)b*NN*CI + (size_t)(m0 + m)*CI + c];
    }
    __syncthreads();
    #pragma unroll
    for (int q = 0; q < 2; q++) {
        int idx2 = tid + q*256;
        {   // Xt[j][m]
            int jl = idx2 >> 4, mo2 = idx2 & 15;
            __half2 h = __floats2half2_rn(s[jl*33 + 2*mo2], s[jl*33 + 2*mo2 + 1]);
            *reinterpret_cast<__half2*>(&g_Xt[(size_t)(b*32 + jl)*NN + m0 + 2*mo2]) = h;
        }
        {   // Xn[m][b*32+c]
            int m = idx2 >> 4, c2 = idx2 & 15;
            __half2 h = __floats2half2_rn(s[(2*c2)*33 + m], s[(2*c2+1)*33 + m]);
            *reinterpret_cast<__half2*>(&g_Xn[(size_t)(m0 + m)*JTOT + b*32 + 2*c2]) = h;
        }
    }
}

// ------ kernel 2: Wh[n][kio] = fp16(sum_d E[n][d] * wp[d][kio]) ------
__global__ void __launch_bounds__(256) k_wgen(const float* __restrict__ E,
                                              const float* __restrict__ wp) {
    const int col2 = blockIdx.x * 256 + threadIdx.x;
    const int n0   = blockIdx.y * 128;
    __shared__ float es[128 * DD];
    for (int t = threadIdx.x; t < 128*DD; t += 256) es[t] = E[n0*DD + t];
    float2 w[DD];
    #pragma unroll
    for (int d = 0; d < DD; d++)
        w[d] = *reinterpret_cast<const float2*>(&wp[d*KIO + 2*col2]);
    __syncthreads();
    #pragma unroll 4
    for (int n = 0; n < 128; n++) {
        float a0 = 0.f, a1 = 0.f;
        #pragma unroll
        for (int d = 0; d < DD; d++) {
            float e = es[n*DD + d];
            a0 = fmaf(e, w[d].x, a0);
            a1 = fmaf(e, w[d].y, a1);
        }
        *reinterpret_cast<__half2*>(&g_Wh[(size_t)(n0 + n)*KIO + 2*col2]) =
            __floats2half2_rn(a0, a1);
    }
}

// ---- kernel 3: fused GEMM + mma-based output epilogue ---------------------
#define NITER   (NN/64)          // 64
#define STAGEB  49152
#define SM_DATA 1024
#define GSMEM   (SM_DATA + 4*STAGEB)   // 197632
// epilogue smem layout (overlaps drained pipeline stages)
#define YA_OFF  0                // YA[node(128)][b(8)][80B] = 81920
#define WS_OFF  81920            // 2 x WBUF0 (8 nodes x 64 rows x 80B = 40960)
#define WBUF0   40960
#define XS_OFF  163840           // 2 x XBUF (8 nodes x 8 b x 80B = 5120)
#define XBUF    5120

__device__ __forceinline__ void issue_loads(uint32_t sbase, int stage, int n0, int col0,
                                            int k0, int tid) {
    const uint32_t sa = sbase + SM_DATA + stage*STAGEB;
    const uint32_t sb = sa + 16384;
    #pragma unroll
    for (int q = 0; q < 4; q++) {
        int gid = tid + q*256;
        int row = gid >> 3, g = gid & 7;
        uint32_t off = row*128 + g*16;
        cp16(sa + SWZ128(off), g_Ph + (size_t)(n0 + row)*NN + k0 + g*8);
    }
    #pragma unroll
    for (int q = 0; q < 8; q++) {
        int gid = tid + q*256;
        int row = gid >> 3, g = gid & 7;
        uint32_t off = row*128 + g*16;
        cp16(sb + SWZ128(off), g_Xt + (size_t)(col0 + row)*NN + k0 + g*8);
    }
    asm volatile("cp.async.commit_group;" ::: "memory");
}

// stage chunk c: 8 nodes of W + Xn slice for THIS CTA's batches (b0..b0+7)
__device__ __forceinline__ void issue_epi(uint32_t sbase, int c, int n0, int b0,
                                          int tid) {
    const int buf = c & 1;
    const uint32_t wdst = sbase + WS_OFF + buf*WBUF0;
    const uint32_t xdst = sbase + XS_OFF + buf*XBUF;
    const int nbase = n0 + c*8;
    #pragma unroll
    for (int q = 0; q < 8; q++) {          // 2048 cp16: ns(8) x row(64) x seg(4)
        int idx = tid + q*256;
        int ns = idx >> 8, rowi = (idx >> 2) & 63, seg = idx & 3;
        cp16(wdst + (uint32_t)(ns*5120 + rowi*80 + seg*16),
             g_Wh + (size_t)(nbase + ns)*KIO + rowi*32 + seg*8);
    }
    {                                       // 256 cp16: ns(8) x b(8) x seg(4)
        int ns = tid >> 5, b = (tid >> 2) & 7, seg = tid & 3;
        cp16(xdst + (uint32_t)(ns*640 + b*80 + seg*16),
             g_Xn + (size_t)(nbase + ns)*JTOT + (b0 + b)*32 + seg*8);  // FIX: +b0
    }
    asm volatile("cp.async.commit_group;" ::: "memory");
}

__global__ void __launch_bounds__(256, 1) k_gemm(float* __restrict__ out) {
    extern __shared__ __align__(1024) uint8_t dsm[];
    const uint32_t sbase = smem_u32(dsm);
    const int tid  = threadIdx.x;
    const int wid  = tid >> 5;
    const int lane = tid & 31;
    const int col0 = blockIdx.x * 256;
    const int n0   = blockIdx.y * 128;
    const int b0   = col0 >> 5;

    const int wm = (wid >> 2) * 64;
    const int wn = (wid & 3) * 64;
    const int r   = lane >> 2;
    const int kg  = lane & 3;

    uint32_t aBase[4], aXor[4];
    {
        int rl = (lane & 7) + ((lane >> 3) & 1) * 8;
        #pragma unroll
        for (int t = 0; t < 4; t++) {
            int row = wm + t*16 + rl;
            aBase[t] = (uint32_t)(row * 128);
            aXor[t]  = (uint32_t)((row & 7) << 4);
        }
    }
    const uint32_t aKc = (uint32_t)(((lane >> 4) & 1) * 16);
    uint32_t bBase[4], bXor[4];
    {
        int jl = ((lane >> 4) & 1) * 8 + (lane & 7);
        #pragma unroll
        for (int p = 0; p < 4; p++) {
            int jr = wn + p*16 + jl;
            bBase[p] = 16384u + (uint32_t)(jr * 128);
            bXor[p]  = (uint32_t)((jr & 7) << 4);
        }
    }
    const uint32_t bKc = (uint32_t)(((lane >> 3) & 1) * 16);

    float acc[4][8][4];
    #pragma unroll
    for (int t = 0; t < 4; t++)
        #pragma unroll
        for (int nt = 0; nt < 8; nt++)
            #pragma unroll
            for (int e = 0; e < 4; e++) acc[t][nt][e] = 0.f;

    issue_loads(sbase, 0, n0, col0, 0,   tid);
    issue_loads(sbase, 1, n0, col0, 64,  tid);
    issue_loads(sbase, 2, n0, col0, 128, tid);

    for (int i = 0; i < NITER; i++) {
        asm volatile("cp.async.wait_group 2;" ::: "memory");
        __syncthreads();
        if (i + 3 < NITER) issue_loads(sbase, (i + 3) & 3, n0, col0, (i + 3)*64, tid);

        const uint32_t cur = sbase + SM_DATA + (i & 3)*STAGEB;
        #pragma unroll
        for (int ks = 0; ks < 4; ks++) {
            const uint32_t ka = (uint32_t)(ks*32) + aKc;
            const uint32_t kb = (uint32_t)(ks*32) + bKc;
            uint32_t a[4][4];
            #pragma unroll
            for (int t = 0; t < 4; t++)
                ldm4(a[t], cur + aBase[t] + (ka ^ aXor[t]));
            uint32_t b[8][2];
            #pragma unroll
            for (int p = 0; p < 4; p++) {
                uint32_t rr[4];
                ldm4(rr, cur + bBase[p] + (kb ^ bXor[p]));
                b[2*p][0]   = rr[0]; b[2*p][1]   = rr[1];
                b[2*p+1][0] = rr[2]; b[2*p+1][1] = rr[3];
            }
            #pragma unroll
            for (int t = 0; t < 4; t++)
                #pragma unroll
                for (int nt = 0; nt < 8; nt++)
                    mma_f16(acc[t][nt], a[t], b[nt]);
        }
    }
    asm volatile("cp.async.wait_group 0;" ::: "memory");
    __syncthreads();

    // ---- stage rinv-scaled Y into YA[node][b][80B] as fp16 ----
    __half* ya_ptr = reinterpret_cast<__half*>(dsm + YA_OFF);
    #pragma unroll
    for (int t = 0; t < 4; t++) {
        const int row0 = wm + t*16 + r;
        const float rv0 = g_rinv[n0 + row0];
        const float rv1 = g_rinv[n0 + row0 + 8];
        #pragma unroll
        for (int nt = 0; nt < 8; nt++) {
            const int col = wn + nt*8 + kg*2;
            const int b = col >> 5, cc = col & 31;
            *reinterpret_cast<__half2*>(&ya_ptr[row0*320 + b*40 + cc]) =
                __floats2half2_rn(acc[t][nt][0]*rv0, acc[t][nt][1]*rv0);
            *reinterpret_cast<__half2*>(&ya_ptr[(row0+8)*320 + b*40 + cc]) =
                __floats2half2_rn(acc[t][nt][2]*rv1, acc[t][nt][3]*rv1);
        }
    }
    issue_epi(sbase, 0, n0, b0, tid);
    issue_epi(sbase, 1, n0, b0, tid);

    // ---- mma epilogue: 16 chunks x 8 nodes, 1 node per warp ----
    const int l8  = lane & 7;
    const int lhi = (lane >> 3) & 1;
    const int bmat = lane >> 3;
    const int bmrow = (lane & 7) + (bmat & 1)*8;
    const int ob = lane >> 2;            // batch row 0..7
    const int oo = (lane & 3) * 2;       // output col pair

    for (int c = 0; c < 16; c++) {
        if (c < 14) asm volatile("cp.async.wait_group 1;" ::: "memory");
        else        asm volatile("cp.async.wait_group 0;" ::: "memory");
        __syncthreads();                 // buffers + YA visible

        const int buf = c & 1;
        const int nl  = c*8 + wid;
        const int n   = n0 + nl;
        const uint32_t xb = sbase + XS_OFF + buf*XBUF + wid*640;
        const uint32_t wb = sbase + WS_OFF + buf*WBUF0 + wid*5120;
        const uint32_t ya = sbase + YA_OFF + (uint32_t)nl*640;

        float C[4][4];
        #pragma unroll
        for (int nt = 0; nt < 4; nt++)
            #pragma unroll
            for (int e = 0; e < 4; e++) C[nt][e] = 0.f;

        #pragma unroll
        for (int ks = 0; ks < 4; ks++) {
            const uint32_t abase = (ks < 2 ? xb : ya);
            uint32_t ar0, ar1;
            ldm2(ar0, ar1, abase + l8*80 + lhi*16 + (ks & 1)*32);
            uint32_t a[4] = {ar0, ar0, ar1, ar1};   // rows 8-15 junk (discarded)
            const uint32_t bb = wb + (uint32_t)((ks*16 + bmrow)*80 + (bmat >> 1)*16);
            uint32_t r1[4], r2[4];
            ldm4t(r1, bb);          // o 0..15
            ldm4t(r2, bb + 32);     // o 16..31
            uint32_t bfr[2];
            bfr[0] = r1[0]; bfr[1] = r1[1]; mma_f16(C[0], a, bfr);
            bfr[0] = r1[2]; bfr[1] = r1[3]; mma_f16(C[1], a, bfr);
            bfr[0] = r2[0]; bfr[1] = r2[1]; mma_f16(C[2], a, bfr);
            bfr[0] = r2[2]; bfr[1] = r2[3]; mma_f16(C[3], a, bfr);
        }
        #pragma unroll
        for (int nt = 0; nt < 4; nt++) {
            const int o = nt*8 + oo;
            float2 bias2 = *reinterpret_cast<const float2*>(&g_bias[n*CO + o]);
            *reinterpret_cast<float2*>(&out[(size_t)(b0 + ob)*NN*CO + (size_t)n*CO + o]) =
                make_float2(C[nt][0] + bias2.x, C[nt][1] + bias2.y);
        }
        __syncthreads();                 // all reads of buffer done
        if (c + 2 < 16) issue_epi(sbase, c + 2, n0, b0, tid);
    }
}

// ---------------- launcher -------------------------------------------------
extern "C" void kernel_launch(void* const* d_in, const int* in_sizes, int n_in,
                              void* d_out, int out_size) {
    const float* x  = (const float*)d_in[0];
    const float* wp = (const float*)d_in[1];
    const float* bp = (const float*)d_in[2];
    const float* E  = (const float*)d_in[3];
    float* out = (float*)d_out;

    static bool attr_done = false;
    if (!attr_done) {
        cudaFuncSetAttribute(k_gemm,     cudaFuncAttributeMaxDynamicSharedMemorySize, GSMEM);
        cudaFuncSetAttribute(k_supports, cudaFuncAttributeMaxDynamicSharedMemorySize, 131072);
        attr_done = true;
    }

    k_supports<<<NN/SROWS, 256, 131072>>>(E, bp);
    dim3 gt(NN/32, BB);
    k_tr<<<gt, 256>>>(x);
    dim3 gw(KIO/512, NN/128);
    k_wgen<<<gw, 256>>>(E, wp);
    dim3 gg(JTOT/256, NN/128);            // (4, 32) = 128 CTAs
    k_gemm<<<gg, 256, GSMEM>>>(out);
}

// round 15
// speedup vs baseline: 1.3579x; 1.0143x over previous
#include <cuda_runtime.h>
#include <cuda_fp16.h>
#include <cstdint>

#define NN   4096
#define DD   16
#define BB   32
#define CI   32
#define CO   32
#define JTOT (BB*CI)     // 1024
#define KIO  (2*CI*CO)   // 2048

// ---------------- scratch ----------------
__device__ __half g_Ph[(size_t)NN*NN];     // 32MB  fp16 exp(v - rowmax)
__device__ float  g_rinv[NN];
__device__ __half g_Wh[(size_t)NN*KIO];    // 16MB  fp16 weights [n][i'=k*32+i][o]
__device__ float  g_bias[(size_t)NN*CO];   // 512KB
__device__ __half g_Xt[(size_t)JTOT*NN];   // 8MB   Xt[j][m] (GEMM B operand)
__device__ __half g_Xn[(size_t)NN*JTOT];   // 8MB   Xn[m][b*32+c] (epilogue A operand)

// ---------------- helpers ----------------
__device__ __forceinline__ uint32_t smem_u32(const void* p) {
    uint32_t a;
    asm("{ .reg .u64 t; cvta.to.shared.u64 t, %1; cvt.u32.u64 %0, t; }" : "=r"(a) : "l"(p));
    return a;
}
union F2 { float2 f; unsigned long long u; };
__device__ __forceinline__ F2 pack2(float x, float y) {
    F2 r; asm("mov.b64 %0, {%1, %2};" : "=l"(r.u) : "f"(x), "f"(y)); return r;
}
__device__ __forceinline__ void fma2(F2& c, F2 a, F2 b) {
    asm("fma.rn.f32x2 %0, %1, %2, %0;" : "+l"(c.u) : "l"(a.u), "l"(b.u));
}
__device__ __forceinline__ void cp16(uint32_t dst, const void* src) {
    asm volatile("cp.async.cg.shared.global [%0], [%1], 16;" :: "r"(dst), "l"(src));
}
__device__ __forceinline__ void ldm4(uint32_t* r, uint32_t addr) {
    asm volatile("ldmatrix.sync.aligned.m8n8.x4.shared.b16 {%0,%1,%2,%3}, [%4];"
                 : "=r"(r[0]), "=r"(r[1]), "=r"(r[2]), "=r"(r[3]) : "r"(addr));
}
__device__ __forceinline__ void ldm4t(uint32_t* r, uint32_t addr) {
    asm volatile("ldmatrix.sync.aligned.m8n8.x4.trans.shared.b16 {%0,%1,%2,%3}, [%4];"
                 : "=r"(r[0]), "=r"(r[1]), "=r"(r[2]), "=r"(r[3]) : "r"(addr));
}
__device__ __forceinline__ void ldm2(uint32_t& r0, uint32_t& r1, uint32_t addr) {
    asm volatile("ldmatrix.sync.aligned.m8n8.x2.shared.b16 {%0,%1}, [%2];"
                 : "=r"(r0), "=r"(r1) : "r"(addr));
}
__device__ __forceinline__ void mma_f16(float* c, const uint32_t* a, const uint32_t* b) {
    asm volatile(
        "mma.sync.aligned.m16n8k16.row.col.f32.f16.f16.f32 "
        "{%0,%1,%2,%3}, {%4,%5,%6,%7}, {%8,%9}, {%0,%1,%2,%3};"
        : "+f"(c[0]), "+f"(c[1]), "+f"(c[2]), "+f"(c[3])
        : "r"(a[0]), "r"(a[1]), "r"(a[2]), "r"(a[3]), "r"(b[0]), "r"(b[1]));
}
#define SWZ128(off) ((off) ^ (((off) >> 3) & 0x70))

// ---- kernel 1: 8 rows/block, 128KB smem logits -> Ph, rinv, bias ----
#define SROWS 8
__global__ void __launch_bounds__(256) k_supports(const float* __restrict__ E,
                                                  const float* __restrict__ bp) {
    extern __shared__ float sL[];
    __shared__ float es[SROWS*DD];
    __shared__ float red[SROWS][8];
    __shared__ float rowred[SROWS];
    const int tid = threadIdx.x;
    const int n0  = blockIdx.x * SROWS;

    if (tid < SROWS*DD) es[tid] = E[n0*DD + tid];
    __syncthreads();
    // pre-packed E pairs: ereg2[r][dd] = (e[2dd], e[2dd+1])
    F2 ereg2[SROWS][DD/2];
    #pragma unroll
    for (int r = 0; r < SROWS; r++)
        #pragma unroll
        for (int dd = 0; dd < DD/2; dd++)
            ereg2[r][dd] = pack2(es[r*DD + 2*dd], es[r*DD + 2*dd + 1]);

    float mx[SROWS];
    #pragma unroll
    for (int r = 0; r < SROWS; r++) mx[r] = 0.f;
    for (int m = tid; m < NN; m += 256) {
        const float4* e4 = reinterpret_cast<const float4*>(E + (size_t)m*DD);
        float4 u0 = e4[0], u1 = e4[1], u2 = e4[2], u3 = e4[3];
        F2 av[8];
        av[0] = pack2(u0.x, u0.y); av[1] = pack2(u0.z, u0.w);
        av[2] = pack2(u1.x, u1.y); av[3] = pack2(u1.z, u1.w);
        av[4] = pack2(u2.x, u2.y); av[5] = pack2(u2.z, u2.w);
        av[6] = pack2(u3.x, u3.y); av[7] = pack2(u3.z, u3.w);
        #pragma unroll
        for (int r = 0; r < SROWS; r++) {
            F2 acc; acc.u = 0ull;
            #pragma unroll
            for (int dd = 0; dd < DD/2; dd++) fma2(acc, av[dd], ereg2[r][dd]);
            float d = fmaxf(acc.f.x + acc.f.y, 0.f);
            sL[r*NN + m] = d;
            mx[r] = fmaxf(mx[r], d);
        }
    }
    #pragma unroll
    for (int r = 0; r < SROWS; r++) {
        float s = mx[r];
        #pragma unroll
        for (int o = 16; o > 0; o >>= 1) s = fmaxf(s, __shfl_xor_sync(0xffffffffu, s, o));
        if ((tid & 31) == 0) red[r][tid >> 5] = s;
    }
    __syncthreads();
    if (tid < SROWS) {
        float t = red[tid][0];
        #pragma unroll
        for (int w = 1; w < 8; w++) t = fmaxf(t, red[tid][w]);
        rowred[tid] = t;
    }
    __syncthreads();
    float rm[SROWS];
    #pragma unroll
    for (int r = 0; r < SROWS; r++) rm[r] = rowred[r];

    float sum[SROWS];
    #pragma unroll
    for (int r = 0; r < SROWS; r++) sum[r] = 0.f;
    for (int m2 = tid; m2 < NN/2; m2 += 256) {
        #pragma unroll
        for (int r = 0; r < SROWS; r++) {
            float2 d = *reinterpret_cast<const float2*>(&sL[r*NN + 2*m2]);
            float p0 = __expf(d.x - rm[r]);
            float p1 = __expf(d.y - rm[r]);
            __half2 h = __floats2half2_rn(p0, p1);
            *reinterpret_cast<__half2*>(&g_Ph[(size_t)(n0 + r)*NN + 2*m2]) = h;
            sum[r] += __half2float(__low2half(h)) + __half2float(__high2half(h));
        }
    }
    #pragma unroll
    for (int r = 0; r < SROWS; r++) {
        float s = sum[r];
        #pragma unroll
        for (int o = 16; o > 0; o >>= 1) s += __shfl_xor_sync(0xffffffffu, s, o);
        if ((tid & 31) == 0) red[r][tid >> 5] = s;
    }
    __syncthreads();
    if (tid < SROWS) {
        float t = 0.f;
        #pragma unroll
        for (int w = 0; w < 8; w++) t += red[tid][w];
        g_rinv[n0 + tid] = 1.0f / t;
    }
    {
        int r = tid >> 5, o = tid & 31;
        float acc = 0.f;
        #pragma unroll
        for (int d = 0; d < DD; d++) acc = fmaf(es[r*DD + d], bp[d*CO + o], acc);
        g_bias[(n0 + r)*CO + o] = acc;
    }
}

// ---- kernel 1b: Xt[j][m] and Xn[m][j] = fp16(x[b,m,c]) ----
__global__ void __launch_bounds__(256) k_tr(const float* __restrict__ x) {
    __shared__ float s[32*33];
    const int tid = threadIdx.x;
    const int b   = blockIdx.y;
    const int m0  = blockIdx.x * 32;
    #pragma unroll
    for (int q = 0; q < 4; q++) {
        int idx = tid + q*256;
        int m = idx >> 5, c = idx & 31;
        s[c*33 + m] = x[(size_t)b*NN*CI + (size_t)(m0 + m)*CI + c];
    }
    __syncthreads();
    #pragma unroll
    for (int q = 0; q < 2; q++) {
        int idx2 = tid + q*256;
        {
            int jl = idx2 >> 4, mo2 = idx2 & 15;
            __half2 h = __floats2half2_rn(s[jl*33 + 2*mo2], s[jl*33 + 2*mo2 + 1]);
            *reinterpret_cast<__half2*>(&g_Xt[(size_t)(b*32 + jl)*NN + m0 + 2*mo2]) = h;
        }
        {
            int m = idx2 >> 4, c2 = idx2 & 15;
            __half2 h = __floats2half2_rn(s[(2*c2)*33 + m], s[(2*c2+1)*33 + m]);
            *reinterpret_cast<__half2*>(&g_Xn[(size_t)(m0 + m)*JTOT + b*32 + 2*c2]) = h;
        }
    }
}

// ------ kernel 2: Wh[n][kio] = fp16(sum_d E[n][d] * wp[d][kio]), f32x2 ------
__global__ void __launch_bounds__(256) k_wgen(const float* __restrict__ E,
                                              const float* __restrict__ wp) {
    const int col2 = blockIdx.x * 256 + threadIdx.x;   // column pair index
    const int n0   = blockIdx.y * 128;
    __shared__ float es[128 * DD];
    for (int t = threadIdx.x; t < 128*DD; t += 256) es[t] = E[n0*DD + t];
    // repack weights by column: wx[dd] = (w[2dd].x, w[2dd+1].x), wy likewise
    F2 wx[DD/2], wy[DD/2];
    #pragma unroll
    for (int dd = 0; dd < DD/2; dd++) {
        float2 wa = *reinterpret_cast<const float2*>(&wp[(2*dd)*KIO + 2*col2]);
        float2 wb = *reinterpret_cast<const float2*>(&wp[(2*dd+1)*KIO + 2*col2]);
        wx[dd] = pack2(wa.x, wb.x);
        wy[dd] = pack2(wa.y, wb.y);
    }
    __syncthreads();
    #pragma unroll 4
    for (int n = 0; n < 128; n++) {
        F2 accx, accy; accx.u = accy.u = 0ull;
        #pragma unroll
        for (int dd = 0; dd < DD/2; dd++) {
            F2 ep; ep.f = *reinterpret_cast<const float2*>(&es[n*DD + 2*dd]);
            fma2(accx, ep, wx[dd]);
            fma2(accy, ep, wy[dd]);
        }
        *reinterpret_cast<__half2*>(&g_Wh[(size_t)(n0 + n)*KIO + 2*col2]) =
            __floats2half2_rn(accx.f.x + accx.f.y, accy.f.x + accy.f.y);
    }
}

// ---- kernel 3: fused GEMM + mma epilogue (3-buffer, 1 barrier/chunk) ------
#define NITER   (NN/64)          // 64
#define STAGEB  49152
#define SM_DATA 1024
// epilogue smem layout
#define YA_OFF  0                // YA[node(128)][b(8)][80B] = 81920
#define WS_OFF  81920            // 3 x WBUF0 (8 nodes x 64 rows x 80B)
#define WBUF0   40960            // -> ends 204800
#define XS_OFF  204800           // 3 x XBUF -> ends 220160
#define XBUF    5120
#define GSMEM   220160           // >= mainloop's 197632

__device__ __forceinline__ void issue_loads(uint32_t sbase, int stage, int n0, int col0,
                                            int k0, int tid) {
    const uint32_t sa = sbase + SM_DATA + stage*STAGEB;
    const uint32_t sb = sa + 16384;
    #pragma unroll
    for (int q = 0; q < 4; q++) {
        int gid = tid + q*256;
        int row = gid >> 3, g = gid & 7;
        uint32_t off = row*128 + g*16;
        cp16(sa + SWZ128(off), g_Ph + (size_t)(n0 + row)*NN + k0 + g*8);
    }
    #pragma unroll
    for (int q = 0; q < 8; q++) {
        int gid = tid + q*256;
        int row = gid >> 3, g = gid & 7;
        uint32_t off = row*128 + g*16;
        cp16(sb + SWZ128(off), g_Xt + (size_t)(col0 + row)*NN + k0 + g*8);
    }
    asm volatile("cp.async.commit_group;" ::: "memory");
}

__device__ __forceinline__ void issue_epi(uint32_t sbase, int c, int n0, int b0,
                                          int tid) {
    const int buf = c % 3;
    const uint32_t wdst = sbase + WS_OFF + buf*WBUF0;
    const uint32_t xdst = sbase + XS_OFF + buf*XBUF;
    const int nbase = n0 + c*8;
    #pragma unroll
    for (int q = 0; q < 8; q++) {
        int idx = tid + q*256;
        int ns = idx >> 8, rowi = (idx >> 2) & 63, seg = idx & 3;
        cp16(wdst + (uint32_t)(ns*5120 + rowi*80 + seg*16),
             g_Wh + (size_t)(nbase + ns)*KIO + rowi*32 + seg*8);
    }
    {
        int ns = tid >> 5, b = (tid >> 2) & 7, seg = tid & 3;
        cp16(xdst + (uint32_t)(ns*640 + b*80 + seg*16),
             g_Xn + (size_t)(nbase + ns)*JTOT + (b0 + b)*32 + seg*8);
    }
    asm volatile("cp.async.commit_group;" ::: "memory");
}

__global__ void __launch_bounds__(256, 1) k_gemm(float* __restrict__ out) {
    extern __shared__ __align__(1024) uint8_t dsm[];
    const uint32_t sbase = smem_u32(dsm);
    const int tid  = threadIdx.x;
    const int wid  = tid >> 5;
    const int lane = tid & 31;
    const int col0 = blockIdx.x * 256;
    const int n0   = blockIdx.y * 128;
    const int b0   = col0 >> 5;

    const int wm = (wid >> 2) * 64;
    const int wn = (wid & 3) * 64;
    const int r   = lane >> 2;
    const int kg  = lane & 3;

    uint32_t aBase[4], aXor[4];
    {
        int rl = (lane & 7) + ((lane >> 3) & 1) * 8;
        #pragma unroll
        for (int t = 0; t < 4; t++) {
            int row = wm + t*16 + rl;
            aBase[t] = (uint32_t)(row * 128);
            aXor[t]  = (uint32_t)((row & 7) << 4);
        }
    }
    const uint32_t aKc = (uint32_t)(((lane >> 4) & 1) * 16);
    uint32_t bBase[4], bXor[4];
    {
        int jl = ((lane >> 4) & 1) * 8 + (lane & 7);
        #pragma unroll
        for (int p = 0; p < 4; p++) {
            int jr = wn + p*16 + jl;
            bBase[p] = 16384u + (uint32_t)(jr * 128);
            bXor[p]  = (uint32_t)((jr & 7) << 4);
        }
    }
    const uint32_t bKc = (uint32_t)(((lane >> 3) & 1) * 16);

    float acc[4][8][4];
    #pragma unroll
    for (int t = 0; t < 4; t++)
        #pragma unroll
        for (int nt = 0; nt < 8; nt++)
            #pragma unroll
            for (int e = 0; e < 4; e++) acc[t][nt][e] = 0.f;

    issue_loads(sbase, 0, n0, col0, 0,   tid);
    issue_loads(sbase, 1, n0, col0, 64,  tid);
    issue_loads(sbase, 2, n0, col0, 128, tid);

    for (int i = 0; i < NITER; i++) {
        asm volatile("cp.async.wait_group 2;" ::: "memory");
        __syncthreads();
        if (i + 3 < NITER) issue_loads(sbase, (i + 3) & 3, n0, col0, (i + 3)*64, tid);

        const uint32_t cur = sbase + SM_DATA + (i & 3)*STAGEB;
        #pragma unroll
        for (int ks = 0; ks < 4; ks++) {
            const uint32_t ka = (uint32_t)(ks*32) + aKc;
            const uint32_t kb = (uint32_t)(ks*32) + bKc;
            uint32_t a[4][4];
            #pragma unroll
            for (int t = 0; t < 4; t++)
                ldm4(a[t], cur + aBase[t] + (ka ^ aXor[t]));
            uint32_t b[8][2];
            #pragma unroll
            for (int p = 0; p < 4; p++) {
                uint32_t rr[4];
                ldm4(rr, cur + bBase[p] + (kb ^ bXor[p]));
                b[2*p][0]   = rr[0]; b[2*p][1]   = rr[1];
                b[2*p+1][0] = rr[2]; b[2*p+1][1] = rr[3];
            }
            #pragma unroll
            for (int t = 0; t < 4; t++)
                #pragma unroll
                for (int nt = 0; nt < 8; nt++)
                    mma_f16(acc[t][nt], a[t], b[nt]);
        }
    }
    asm volatile("cp.async.wait_group 0;" ::: "memory");
    __syncthreads();

    // ---- stage rinv-scaled Y into YA[node][b][80B] as fp16 ----
    __half* ya_ptr = reinterpret_cast<__half*>(dsm + YA_OFF);
    #pragma unroll
    for (int t = 0; t < 4; t++) {
        const int row0 = wm + t*16 + r;
        const float rv0 = g_rinv[n0 + row0];
        const float rv1 = g_rinv[n0 + row0 + 8];
        #pragma unroll
        for (int nt = 0; nt < 8; nt++) {
            const int col = wn + nt*8 + kg*2;
            const int b = col >> 5, cc = col & 31;
            *reinterpret_cast<__half2*>(&ya_ptr[row0*320 + b*40 + cc]) =
                __floats2half2_rn(acc[t][nt][0]*rv0, acc[t][nt][1]*rv0);
            *reinterpret_cast<__half2*>(&ya_ptr[(row0+8)*320 + b*40 + cc]) =
                __floats2half2_rn(acc[t][nt][2]*rv1, acc[t][nt][3]*rv1);
        }
    }
    issue_epi(sbase, 0, n0, b0, tid);
    issue_epi(sbase, 1, n0, b0, tid);

    // ---- mma epilogue: 16 chunks x 8 nodes, ONE barrier per chunk ----
    const int l8  = lane & 7;
    const int lhi = (lane >> 3) & 1;
    const int bmat = lane >> 3;
    const int bmrow = (lane & 7) + (bmat & 1)*8;
    const int ob = lane >> 2;
    const int oo = (lane & 3) * 2;

    for (int c = 0; c < 16; c++) {
        if (c < 15) asm volatile("cp.async.wait_group 1;" ::: "memory");
        else        asm volatile("cp.async.wait_group 0;" ::: "memory");
        __syncthreads();                 // buffer c visible; chunk c-1 reads done
        if (c + 2 < 16) issue_epi(sbase, c + 2, n0, b0, tid);

        const int buf = c % 3;
        const int nl  = c*8 + wid;
        const int n   = n0 + nl;
        const uint32_t xb = sbase + XS_OFF + buf*XBUF + wid*640;
        const uint32_t wb = sbase + WS_OFF + buf*WBUF0 + wid*5120;
        const uint32_t ya = sbase + YA_OFF + (uint32_t)nl*640;

        float C[4][4];
        #pragma unroll
        for (int nt = 0; nt < 4; nt++)
            #pragma unroll
            for (int e = 0; e < 4; e++) C[nt][e] = 0.f;

        #pragma unroll
        for (int ks = 0; ks < 4; ks++) {
            const uint32_t abase = (ks < 2 ? xb : ya);
            uint32_t ar0, ar1;
            ldm2(ar0, ar1, abase + l8*80 + lhi*16 + (ks & 1)*32);
            uint32_t a[4] = {ar0, ar0, ar1, ar1};
            const uint32_t bb = wb + (uint32_t)((ks*16 + bmrow)*80 + (bmat >> 1)*16);
            uint32_t r1[4], r2[4];
            ldm4t(r1, bb);
            ldm4t(r2, bb + 32);
            uint32_t bfr[2];
            bfr[0] = r1[0]; bfr[1] = r1[1]; mma_f16(C[0], a, bfr);
            bfr[0] = r1[2]; bfr[1] = r1[3]; mma_f16(C[1], a, bfr);
            bfr[0] = r2[0]; bfr[1] = r2[1]; mma_f16(C[2], a, bfr);
            bfr[0] = r2[2]; bfr[1] = r2[3]; mma_f16(C[3], a, bfr);
        }
        #pragma unroll
        for (int nt = 0; nt < 4; nt++) {
            const int o = nt*8 + oo;
            float2 bias2 = *reinterpret_cast<const float2*>(&g_bias[n*CO + o]);
            *reinterpret_cast<float2*>(&out[(size_t)(b0 + ob)*NN*CO + (size_t)n*CO + o]) =
                make_float2(C[nt][0] + bias2.x, C[nt][1] + bias2.y);
        }
    }
}

// ---------------- launcher -------------------------------------------------
extern "C" void kernel_launch(void* const* d_in, const int* in_sizes, int n_in,
                              void* d_out, int out_size) {
    const float* x  = (const float*)d_in[0];
    const float* wp = (const float*)d_in[1];
    const float* bp = (const float*)d_in[2];
    const float* E  = (const float*)d_in[3];
    float* out = (float*)d_out;

    static bool attr_done = false;
    if (!attr_done) {
        cudaFuncSetAttribute(k_gemm,     cudaFuncAttributeMaxDynamicSharedMemorySize, GSMEM);
        cudaFuncSetAttribute(k_supports, cudaFuncAttributeMaxDynamicSharedMemorySize, 131072);
        attr_done = true;
    }

    k_supports<<<NN/SROWS, 256, 131072>>>(E, bp);
    dim3 gt(NN/32, BB);
    k_tr<<<gt, 256>>>(x);
    dim3 gw(KIO/512, NN/128);
    k_wgen<<<gw, 256>>>(E, wp);
    dim3 gg(JTOT/256, NN/128);            // (4, 32) = 128 CTAs
    k_gemm<<<gg, 256, GSMEM>>>(out);
}

// round 16
// speedup vs baseline: 1.4331x; 1.0554x over previous
#include <cuda_runtime.h>
#include <cuda_fp16.h>
#include <cstdint>

#define NN   4096
#define DD   16
#define BB   32
#define CI   32
#define CO   32
#define JTOT (BB*CI)     // 1024
#define KIO  (2*CI*CO)   // 2048

// ---------------- scratch ----------------
__device__ __half g_Ph[(size_t)NN*NN];     // 32MB  fp16 exp(v - rowmax)
__device__ float  g_rinv[NN];
__device__ __half g_Wh[(size_t)NN*KIO];    // 16MB  fp16 weights [n][i'=k*32+i][o]
__device__ float  g_bias[(size_t)NN*CO];   // 512KB
__device__ __half g_Xt[(size_t)JTOT*NN];   // 8MB   Xt[j][m] (GEMM B operand)
__device__ __half g_Xn[(size_t)NN*JTOT];   // 8MB   Xn[m][b*32+c]
__device__ __half g_Ya[(size_t)NN*JTOT];   // 8MB   Ya[n][b*32+c] = fp16(rinv*Y)

// ---------------- helpers ----------------
__device__ __forceinline__ uint32_t smem_u32(const void* p) {
    uint32_t a;
    asm("{ .reg .u64 t; cvta.to.shared.u64 t, %1; cvt.u32.u64 %0, t; }" : "=r"(a) : "l"(p));
    return a;
}
union F2 { float2 f; unsigned long long u; };
__device__ __forceinline__ F2 pack2(float x, float y) {
    F2 r; asm("mov.b64 %0, {%1, %2};" : "=l"(r.u) : "f"(x), "f"(y)); return r;
}
__device__ __forceinline__ void fma2(F2& c, F2 a, F2 b) {
    asm("fma.rn.f32x2 %0, %1, %2, %0;" : "+l"(c.u) : "l"(a.u), "l"(b.u));
}
__device__ __forceinline__ void cp16(uint32_t dst, const void* src) {
    asm volatile("cp.async.cg.shared.global [%0], [%1], 16;" :: "r"(dst), "l"(src));
}
__device__ __forceinline__ void ldm4(uint32_t* r, uint32_t addr) {
    asm volatile("ldmatrix.sync.aligned.m8n8.x4.shared.b16 {%0,%1,%2,%3}, [%4];"
                 : "=r"(r[0]), "=r"(r[1]), "=r"(r[2]), "=r"(r[3]) : "r"(addr));
}
__device__ __forceinline__ void ldm4t(uint32_t* r, uint32_t addr) {
    asm volatile("ldmatrix.sync.aligned.m8n8.x4.trans.shared.b16 {%0,%1,%2,%3}, [%4];"
                 : "=r"(r[0]), "=r"(r[1]), "=r"(r[2]), "=r"(r[3]) : "r"(addr));
}
__device__ __forceinline__ void mma_f16(float* c, const uint32_t* a, const uint32_t* b) {
    asm volatile(
        "mma.sync.aligned.m16n8k16.row.col.f32.f16.f16.f32 "
        "{%0,%1,%2,%3}, {%4,%5,%6,%7}, {%8,%9}, {%0,%1,%2,%3};"
        : "+f"(c[0]), "+f"(c[1]), "+f"(c[2]), "+f"(c[3])
        : "r"(a[0]), "r"(a[1]), "r"(a[2]), "r"(a[3]), "r"(b[0]), "r"(b[1]));
}
#define SWZ128(off) ((off) ^ (((off) >> 3) & 0x70))

// ---- kernel 1: 8 rows/block, 128KB smem logits -> Ph, rinv, bias ----
#define SROWS 8
__global__ void __launch_bounds__(256) k_supports(const float* __restrict__ E,
                                                  const float* __restrict__ bp) {
    extern __shared__ float sL[];
    __shared__ float es[SROWS*DD];
    __shared__ float red[SROWS][8];
    __shared__ float rowred[SROWS];
    const int tid = threadIdx.x;
    const int n0  = blockIdx.x * SROWS;

    if (tid < SROWS*DD) es[tid] = E[n0*DD + tid];
    __syncthreads();
    F2 ereg2[SROWS][DD/2];
    #pragma unroll
    for (int r = 0; r < SROWS; r++)
        #pragma unroll
        for (int dd = 0; dd < DD/2; dd++)
            ereg2[r][dd] = pack2(es[r*DD + 2*dd], es[r*DD + 2*dd + 1]);

    float mx[SROWS];
    #pragma unroll
    for (int r = 0; r < SROWS; r++) mx[r] = 0.f;
    for (int m = tid; m < NN; m += 256) {
        const float4* e4 = reinterpret_cast<const float4*>(E + (size_t)m*DD);
        float4 u0 = e4[0], u1 = e4[1], u2 = e4[2], u3 = e4[3];
        F2 av[8];
        av[0] = pack2(u0.x, u0.y); av[1] = pack2(u0.z, u0.w);
        av[2] = pack2(u1.x, u1.y); av[3] = pack2(u1.z, u1.w);
        av[4] = pack2(u2.x, u2.y); av[5] = pack2(u2.z, u2.w);
        av[6] = pack2(u3.x, u3.y); av[7] = pack2(u3.z, u3.w);
        #pragma unroll
        for (int r = 0; r < SROWS; r++) {
            F2 acc; acc.u = 0ull;
            #pragma unroll
            for (int dd = 0; dd < DD/2; dd++) fma2(acc, av[dd], ereg2[r][dd]);
            float d = fmaxf(acc.f.x + acc.f.y, 0.f);
            sL[r*NN + m] = d;
            mx[r] = fmaxf(mx[r], d);
        }
    }
    #pragma unroll
    for (int r = 0; r < SROWS; r++) {
        float s = mx[r];
        #pragma unroll
        for (int o = 16; o > 0; o >>= 1) s = fmaxf(s, __shfl_xor_sync(0xffffffffu, s, o));
        if ((tid & 31) == 0) red[r][tid >> 5] = s;
    }
    __syncthreads();
    if (tid < SROWS) {
        float t = red[tid][0];
        #pragma unroll
        for (int w = 1; w < 8; w++) t = fmaxf(t, red[tid][w]);
        rowred[tid] = t;
    }
    __syncthreads();
    float rm[SROWS];
    #pragma unroll
    for (int r = 0; r < SROWS; r++) rm[r] = rowred[r];

    float sum[SROWS];
    #pragma unroll
    for (int r = 0; r < SROWS; r++) sum[r] = 0.f;
    for (int m2 = tid; m2 < NN/2; m2 += 256) {
        #pragma unroll
        for (int r = 0; r < SROWS; r++) {
            float2 d = *reinterpret_cast<const float2*>(&sL[r*NN + 2*m2]);
            float p0 = __expf(d.x - rm[r]);
            float p1 = __expf(d.y - rm[r]);
            __half2 h = __floats2half2_rn(p0, p1);
            *reinterpret_cast<__half2*>(&g_Ph[(size_t)(n0 + r)*NN + 2*m2]) = h;
            sum[r] += __half2float(__low2half(h)) + __half2float(__high2half(h));
        }
    }
    #pragma unroll
    for (int r = 0; r < SROWS; r++) {
        float s = sum[r];
        #pragma unroll
        for (int o = 16; o > 0; o >>= 1) s += __shfl_xor_sync(0xffffffffu, s, o);
        if ((tid & 31) == 0) red[r][tid >> 5] = s;
    }
    __syncthreads();
    if (tid < SROWS) {
        float t = 0.f;
        #pragma unroll
        for (int w = 0; w < 8; w++) t += red[tid][w];
        g_rinv[n0 + tid] = 1.0f / t;
    }
    {
        int r = tid >> 5, o = tid & 31;
        float acc = 0.f;
        #pragma unroll
        for (int d = 0; d < DD; d++) acc = fmaf(es[r*DD + d], bp[d*CO + o], acc);
        g_bias[(n0 + r)*CO + o] = acc;
    }
}

// ---- kernel 1b: Xt[j][m] and Xn[m][j] = fp16(x[b,m,c]) ----
__global__ void __launch_bounds__(256) k_tr(const float* __restrict__ x) {
    __shared__ float s[32*33];
    const int tid = threadIdx.x;
    const int b   = blockIdx.y;
    const int m0  = blockIdx.x * 32;
    #pragma unroll
    for (int q = 0; q < 4; q++) {
        int idx = tid + q*256;
        int m = idx >> 5, c = idx & 31;
        s[c*33 + m] = x[(size_t)b*NN*CI + (size_t)(m0 + m)*CI + c];
    }
    __syncthreads();
    #pragma unroll
    for (int q = 0; q < 2; q++) {
        int idx2 = tid + q*256;
        {
            int jl = idx2 >> 4, mo2 = idx2 & 15;
            __half2 h = __floats2half2_rn(s[jl*33 + 2*mo2], s[jl*33 + 2*mo2 + 1]);
            *reinterpret_cast<__half2*>(&g_Xt[(size_t)(b*32 + jl)*NN + m0 + 2*mo2]) = h;
        }
        {
            int m = idx2 >> 4, c2 = idx2 & 15;
            __half2 h = __floats2half2_rn(s[(2*c2)*33 + m], s[(2*c2+1)*33 + m]);
            *reinterpret_cast<__half2*>(&g_Xn[(size_t)(m0 + m)*JTOT + b*32 + 2*c2]) = h;
        }
    }
}

// ------ kernel 2: Wh[n][kio] = fp16(sum_d E[n][d] * wp[d][kio]), f32x2 ------
__global__ void __launch_bounds__(256) k_wgen(const float* __restrict__ E,
                                              const float* __restrict__ wp) {
    const int col2 = blockIdx.x * 256 + threadIdx.x;
    const int n0   = blockIdx.y * 128;
    __shared__ float es[128 * DD];
    for (int t = threadIdx.x; t < 128*DD; t += 256) es[t] = E[n0*DD + t];
    F2 wx[DD/2], wy[DD/2];
    #pragma unroll
    for (int dd = 0; dd < DD/2; dd++) {
        float2 wa = *reinterpret_cast<const float2*>(&wp[(2*dd)*KIO + 2*col2]);
        float2 wb = *reinterpret_cast<const float2*>(&wp[(2*dd+1)*KIO + 2*col2]);
        wx[dd] = pack2(wa.x, wb.x);
        wy[dd] = pack2(wa.y, wb.y);
    }
    __syncthreads();
    #pragma unroll 4
    for (int n = 0; n < 128; n++) {
        F2 accx, accy; accx.u = accy.u = 0ull;
        #pragma unroll
        for (int dd = 0; dd < DD/2; dd++) {
            F2 ep; ep.f = *reinterpret_cast<const float2*>(&es[n*DD + 2*dd]);
            fma2(accx, ep, wx[dd]);
            fma2(accy, ep, wy[dd]);
        }
        *reinterpret_cast<__half2*>(&g_Wh[(size_t)(n0 + n)*KIO + 2*col2]) =
            __floats2half2_rn(accx.f.x + accx.f.y, accy.f.x + accy.f.y);
    }
}

// ---- kernel 3: GEMM mainloop -> g_Ya (fp16, rinv folded) ------------------
#define NITER   (NN/64)          // 64
#define STAGEB  49152
#define SM_DATA 1024
#define GSMEM   (SM_DATA + 4*STAGEB)   // 197632
#define YA_OFF  0                // YA[row(128)][b(8)][80B] = 81920 (overlays stages)

__device__ __forceinline__ void issue_loads(uint32_t sbase, int stage, int n0, int col0,
                                            int k0, int tid) {
    const uint32_t sa = sbase + SM_DATA + stage*STAGEB;
    const uint32_t sb = sa + 16384;
    #pragma unroll
    for (int q = 0; q < 4; q++) {
        int gid = tid + q*256;
        int row = gid >> 3, g = gid & 7;
        uint32_t off = row*128 + g*16;
        cp16(sa + SWZ128(off), g_Ph + (size_t)(n0 + row)*NN + k0 + g*8);
    }
    #pragma unroll
    for (int q = 0; q < 8; q++) {
        int gid = tid + q*256;
        int row = gid >> 3, g = gid & 7;
        uint32_t off = row*128 + g*16;
        cp16(sb + SWZ128(off), g_Xt + (size_t)(col0 + row)*NN + k0 + g*8);
    }
    asm volatile("cp.async.commit_group;" ::: "memory");
}

__global__ void __launch_bounds__(256, 1) k_gemm() {
    extern __shared__ __align__(1024) uint8_t dsm[];
    const uint32_t sbase = smem_u32(dsm);
    const int tid  = threadIdx.x;
    const int wid  = tid >> 5;
    const int lane = tid & 31;
    const int col0 = blockIdx.x * 256;
    const int n0   = blockIdx.y * 128;
    const int b0   = col0 >> 5;

    const int wm = (wid >> 2) * 64;
    const int wn = (wid & 3) * 64;
    const int r   = lane >> 2;
    const int kg  = lane & 3;

    uint32_t aBase[4], aXor[4];
    {
        int rl = (lane & 7) + ((lane >> 3) & 1) * 8;
        #pragma unroll
        for (int t = 0; t < 4; t++) {
            int row = wm + t*16 + rl;
            aBase[t] = (uint32_t)(row * 128);
            aXor[t]  = (uint32_t)((row & 7) << 4);
        }
    }
    const uint32_t aKc = (uint32_t)(((lane >> 4) & 1) * 16);
    uint32_t bBase[4], bXor[4];
    {
        int jl = ((lane >> 4) & 1) * 8 + (lane & 7);
        #pragma unroll
        for (int p = 0; p < 4; p++) {
            int jr = wn + p*16 + jl;
            bBase[p] = 16384u + (uint32_t)(jr * 128);
            bXor[p]  = (uint32_t)((jr & 7) << 4);
        }
    }
    const uint32_t bKc = (uint32_t)(((lane >> 3) & 1) * 16);

    float acc[4][8][4];
    #pragma unroll
    for (int t = 0; t < 4; t++)
        #pragma unroll
        for (int nt = 0; nt < 8; nt++)
            #pragma unroll
            for (int e = 0; e < 4; e++) acc[t][nt][e] = 0.f;

    issue_loads(sbase, 0, n0, col0, 0,   tid);
    issue_loads(sbase, 1, n0, col0, 64,  tid);
    issue_loads(sbase, 2, n0, col0, 128, tid);

    for (int i = 0; i < NITER; i++) {
        asm volatile("cp.async.wait_group 2;" ::: "memory");
        __syncthreads();
        if (i + 3 < NITER) issue_loads(sbase, (i + 3) & 3, n0, col0, (i + 3)*64, tid);

        const uint32_t cur = sbase + SM_DATA + (i & 3)*STAGEB;
        #pragma unroll
        for (int ks = 0; ks < 4; ks++) {
            const uint32_t ka = (uint32_t)(ks*32) + aKc;
            const uint32_t kb = (uint32_t)(ks*32) + bKc;
            uint32_t a[4][4];
            #pragma unroll
            for (int t = 0; t < 4; t++)
                ldm4(a[t], cur + aBase[t] + (ka ^ aXor[t]));
            uint32_t b[8][2];
            #pragma unroll
            for (int p = 0; p < 4; p++) {
                uint32_t rr[4];
                ldm4(rr, cur + bBase[p] + (kb ^ bXor[p]));
                b[2*p][0]   = rr[0]; b[2*p][1]   = rr[1];
                b[2*p+1][0] = rr[2]; b[2*p+1][1] = rr[3];
            }
            #pragma unroll
            for (int t = 0; t < 4; t++)
                #pragma unroll
                for (int nt = 0; nt < 8; nt++)
                    mma_f16(acc[t][nt], a[t], b[nt]);
        }
    }
    asm volatile("cp.async.wait_group 0;" ::: "memory");
    __syncthreads();

    // stage rinv-scaled Y as fp16 into smem, then coalesced dump to g_Ya
    __half* ya_ptr = reinterpret_cast<__half*>(dsm + YA_OFF);
    #pragma unroll
    for (int t = 0; t < 4; t++) {
        const int row0 = wm + t*16 + r;
        const float rv0 = g_rinv[n0 + row0];
        const float rv1 = g_rinv[n0 + row0 + 8];
        #pragma unroll
        for (int nt = 0; nt < 8; nt++) {
            const int col = wn + nt*8 + kg*2;
            const int b = col >> 5, cc = col & 31;
            *reinterpret_cast<__half2*>(&ya_ptr[row0*320 + b*40 + cc]) =
                __floats2half2_rn(acc[t][nt][0]*rv0, acc[t][nt][1]*rv0);
            *reinterpret_cast<__half2*>(&ya_ptr[(row0+8)*320 + b*40 + cc]) =
                __floats2half2_rn(acc[t][nt][2]*rv1, acc[t][nt][3]*rv1);
        }
    }
    __syncthreads();
    #pragma unroll
    for (int q = 0; q < 16; q++) {
        int flat = tid + q*256;                  // 4096 float4 chunks
        int rowi = flat >> 5, b = (flat >> 2) & 7, seg = flat & 3;
        float4 v = *reinterpret_cast<const float4*>(
            reinterpret_cast<const uint8_t*>(ya_ptr) + rowi*640 + b*80 + seg*16);
        *reinterpret_cast<float4*>(&g_Ya[(size_t)(n0 + rowi)*JTOT + (b0 + b)*32 + seg*8]) = v;
    }
}

// ---- kernel 4: mma output epilogue, 8 nodes/CTA, 2 CTA/SM -----------------
#define OANODE  4608             // 32 rows x 144B
#define OW_OFF  36864            // 8 x 4608
#define OWNODE  5120             // 64 rows x 80B
#define OSMEM   77824            // + 8 x 5120

__global__ void __launch_bounds__(256, 2) k_out2(float* __restrict__ out) {
    extern __shared__ __align__(1024) uint8_t dsm[];
    const uint32_t sbase = smem_u32(dsm);
    const int tid  = threadIdx.x;
    const int wid  = tid >> 5;
    const int lane = tid & 31;
    const int n0   = blockIdx.x * 8;

    // stage A = [x | ya] : 2048 cp16 (ns x b x seg8: 0-3 x, 4-7 ya)
    #pragma unroll
    for (int q = 0; q < 8; q++) {
        int idx = tid + q*256;
        int ns = idx >> 8, rem = idx & 255;
        int b = rem >> 3, s = rem & 7;
        uint32_t dst = sbase + (uint32_t)(ns*OANODE + b*144 + s*16);
        const __half* src = (s < 4)
            ? g_Xn + (size_t)(n0 + ns)*JTOT + b*32 + s*8
            : g_Ya + (size_t)(n0 + ns)*JTOT + b*32 + (s - 4)*8;
        cp16(dst, src);
    }
    // stage W : 2048 cp16 (identical layout to proven R15 path)
    #pragma unroll
    for (int q = 0; q < 8; q++) {
        int idx = tid + q*256;
        int ns = idx >> 8, rowi = (idx >> 2) & 63, seg = idx & 3;
        cp16(sbase + OW_OFF + (uint32_t)(ns*OWNODE + rowi*80 + seg*16),
             g_Wh + (size_t)(n0 + ns)*KIO + rowi*32 + seg*8);
    }
    asm volatile("cp.async.commit_group;" ::: "memory");
    asm volatile("cp.async.wait_group 0;" ::: "memory");
    __syncthreads();

    const int n  = n0 + wid;
    const uint32_t ab = sbase + (uint32_t)(wid*OANODE);
    const uint32_t wb = sbase + OW_OFF + (uint32_t)(wid*OWNODE);
    const int arow = lane & 15;
    const uint32_t ahi  = (uint32_t)(((lane >> 4) & 1) * 16);
    const int bmat  = lane >> 3;
    const int bmrow = (lane & 7) + (bmat & 1)*8;

    float C[2][4][4];
    #pragma unroll
    for (int t = 0; t < 2; t++)
        #pragma unroll
        for (int nt = 0; nt < 4; nt++)
            #pragma unroll
            for (int e = 0; e < 4; e++) C[t][nt][e] = 0.f;

    #pragma unroll
    for (int ks = 0; ks < 4; ks++) {
        uint32_t a[2][4];
        #pragma unroll
        for (int t = 0; t < 2; t++)
            ldm4(a[t], ab + (uint32_t)((t*16 + arow)*144 + ks*32) + ahi);
        const uint32_t bb = wb + (uint32_t)((ks*16 + bmrow)*80 + (bmat >> 1)*16);
        uint32_t r1[4], r2[4];
        ldm4t(r1, bb);          // o 0..15
        ldm4t(r2, bb + 32);     // o 16..31
        uint32_t bfr[2];
        #pragma unroll
        for (int t = 0; t < 2; t++) {
            bfr[0] = r1[0]; bfr[1] = r1[1]; mma_f16(C[t][0], a[t], bfr);
            bfr[0] = r1[2]; bfr[1] = r1[3]; mma_f16(C[t][1], a[t], bfr);
            bfr[0] = r2[0]; bfr[1] = r2[1]; mma_f16(C[t][2], a[t], bfr);
            bfr[0] = r2[2]; bfr[1] = r2[3]; mma_f16(C[t][3], a[t], bfr);
        }
    }

    const int rb = lane >> 2;
    const int oo = (lane & 3) * 2;
    #pragma unroll
    for (int t = 0; t < 2; t++) {
        #pragma unroll
        for (int nt = 0; nt < 4; nt++) {
            const int o = nt*8 + oo;
            float2 bias2 = *reinterpret_cast<const float2*>(&g_bias[n*CO + o]);
            const int b_lo = t*16 + rb;
            *reinterpret_cast<float2*>(&out[(size_t)b_lo*NN*CO + (size_t)n*CO + o]) =
                make_float2(C[t][nt][0] + bias2.x, C[t][nt][1] + bias2.y);
            *reinterpret_cast<float2*>(&out[(size_t)(b_lo+8)*NN*CO + (size_t)n*CO + o]) =
                make_float2(C[t][nt][2] + bias2.x, C[t][nt][3] + bias2.y);
        }
    }
}

// ---------------- launcher -------------------------------------------------
extern "C" void kernel_launch(void* const* d_in, const int* in_sizes, int n_in,
                              void* d_out, int out_size) {
    const float* x  = (const float*)d_in[0];
    const float* wp = (const float*)d_in[1];
    const float* bp = (const float*)d_in[2];
    const float* E  = (const float*)d_in[3];
    float* out = (float*)d_out;

    static bool attr_done = false;
    if (!attr_done) {
        cudaFuncSetAttribute(k_gemm,     cudaFuncAttributeMaxDynamicSharedMemorySize, GSMEM);
        cudaFuncSetAttribute(k_supports, cudaFuncAttributeMaxDynamicSharedMemorySize, 131072);
        cudaFuncSetAttribute(k_out2,     cudaFuncAttributeMaxDynamicSharedMemorySize, OSMEM);
        attr_done = true;
    }

    k_supports<<<NN/SROWS, 256, 131072>>>(E, bp);
    dim3 gt(NN/32, BB);
    k_tr<<<gt, 256>>>(x);
    dim3 gw(KIO/512, NN/128);
    k_wgen<<<gw, 256>>>(E, wp);
    dim3 gg(JTOT/256, NN/128);            // (4, 32) = 128 CTAs
    k_gemm<<<gg, 256, GSMEM>>>();
    k_out2<<<NN/8, 256, OSMEM>>>(out);
}